// round 12
// baseline (speedup 1.0000x reference)
#include <cuda_runtime.h>
#include <cuda_bf16.h>
#include <math.h>
#include <stdint.h>

#define EE   400
#define HH   1150
#define VV   10000
#define TT   256
#define BB   32
#define M4H  4600
#define NROW 8192
typedef unsigned long long ull;

template<int L> struct LC;
template<> struct LC<0>{ enum{OUT=1150,NJB=36,NCH=18,S=4,KX=0,   KH=1150}; };
template<> struct LC<1>{ enum{OUT=1150,NJB=36,NCH=36,S=4,KX=1150,KH=1150}; };
template<> struct LC<2>{ enum{OUT=400, NJB=13,NCH=25,S=8,KX=1150,KH=400 }; };

// ---------------- device scratch ----------------
__device__ __align__(16) float g_P0[(size_t)NROW * M4H];
__device__ __align__(16) float g_h2all[(size_t)NROW * EE];
__device__ __align__(16) float g_c[3][HH * BB];
__device__ __align__(16) float g_hf[3][HH * BB];
__device__ __align__(16) __nv_bfloat16 gA0[(size_t)36*18*16384];
__device__ __align__(16) __nv_bfloat16 gA1[(size_t)36*36*16384];
__device__ __align__(16) __nv_bfloat16 gA2[(size_t)13*25*16384];
__device__ __align__(16) __nv_bfloat16 gB0[2][18*4096];
__device__ __align__(16) __nv_bfloat16 gB1[2][36*4096];
__device__ __align__(16) __nv_bfloat16 gB2[2][25*4096];
__device__ __align__(16) float gPart0[36*4*4096];
__device__ __align__(16) float gPart1[36*4*4096];
__device__ __align__(16) float gPart2[13*8*4096];
__device__ int g_cnt[3][36];   // zero-init; reset by consumer each launch

template<int L> __device__ __forceinline__ __nv_bfloat16* Apack(){
    return (L==0) ? gA0 : (L==1) ? gA1 : gA2;
}
template<int L> __device__ __forceinline__ __nv_bfloat16* Bpack(int par){
    return (L==0) ? gB0[par] : (L==1) ? gB1[par] : gB2[par];
}
template<int L> __device__ __forceinline__ float* Ppart(){
    return (L==0) ? gPart0 : (L==1) ? gPart1 : gPart2;
}

// ---------------- helpers ----------------
#define SWZ(x) ((x) ^ (((x) >> 3) & 0x70))
__device__ __forceinline__ uint32_t smem_u32(const void* p){
    uint32_t a;
    asm("{ .reg .u64 t; cvta.to.shared.u64 t, %1; cvt.u32.u64 %0, t; }" : "=r"(a) : "l"(p));
    return a;
}
__device__ __forceinline__ void cpa16(uint32_t dst, const void* src){
    asm volatile("cp.async.ca.shared.global [%0], [%1], 16;" :: "r"(dst), "l"(src));
}
#define CPA_COMMIT() asm volatile("cp.async.commit_group;" ::: "memory")

// write one h value as bf16 hi/lo into a preswizzled 32x64 B tile
__device__ __forceinline__ void stageB(__nv_bfloat16* base, int kabs, int b, float v){
    int c = kabs >> 6, kk = kabs & 63;
    uint32_t pos = SWZ((uint32_t)(b*128 + kk*2)) >> 1;
    __nv_bfloat16 h = __float2bfloat16(v);
    base[(size_t)c*4096 + pos]        = h;
    base[(size_t)c*4096 + 2048 + pos] = __float2bfloat16(v - __bfloat162float(h));
}

// f32x2 (for the fp32 GEMMs)
__device__ __forceinline__ void fma2(ull& d, ull a, ull b){
    asm("fma.rn.f32x2 %0, %1, %2, %0;" : "+l"(d) : "l"(a), "l"(b));
}
__device__ __forceinline__ ull dup2(float x){
    ull r; asm("mov.b64 %0, {%1, %2};" : "=l"(r) : "f"(x), "f"(x)); return r;
}
__device__ __forceinline__ float2 unp2(ull v){
    float2 r; asm("mov.b64 {%0, %1}, %2;" : "=f"(r.x), "=f"(r.y) : "l"(v)); return r;
}

// =======================================================================
// fp32 SGEMM (proven): C[M,N] = A[M,400]*Bm[N,400]^T + bias
// =======================================================================
template<int MODE>
__global__ __launch_bounds__(256) void sgemm_nt(
    const float* __restrict__ A, const int* __restrict__ gidx,
    const float* __restrict__ Bm, const float* __restrict__ bias,
    float* __restrict__ Cout, int N)
{
    const int K = EE;
    __shared__ __align__(16) float As[16][68];
    __shared__ __align__(16) float Bs[16][68];
    float* C = (MODE==0) ? g_P0 : Cout;
    const float* Abase = (MODE==1) ? g_h2all : A;
    const int tid = threadIdx.x;
    const int bm = blockIdx.y*64, bn = blockIdx.x*64;
    const int r = tid>>2, q = tid&3;
    const float* arow = (MODE==0) ? Abase + (size_t)gidx[bm+r]*K : Abase + (size_t)(bm+r)*K;
    const int nrow = bn + r;
    const bool bok = nrow < N;
    const float* brow = Bm + (size_t)(bok ? nrow : (N-1))*K;
    const int tx = tid&15, ty = tid>>4;
    ull acc[4][2];
#pragma unroll
    for (int i=0;i<4;++i){ acc[i][0]=0ull; acc[i][1]=0ull; }
    for (int kc=0;kc<K;kc+=16){
        float4 av = *(const float4*)(arow + kc + q*4);
        float4 bv = *(const float4*)(brow + kc + q*4);
        if (!bok){ bv.x=bv.y=bv.z=bv.w=0.f; }
        __syncthreads();
        As[q*4+0][r]=av.x; As[q*4+1][r]=av.y; As[q*4+2][r]=av.z; As[q*4+3][r]=av.w;
        Bs[q*4+0][r]=bv.x; Bs[q*4+1][r]=bv.y; Bs[q*4+2][r]=bv.z; Bs[q*4+3][r]=bv.w;
        __syncthreads();
#pragma unroll
        for (int k=0;k<16;++k){
            ull b0 = *(const ull*)&Bs[k][tx*4];
            ull b1 = *(const ull*)&Bs[k][tx*4+2];
            float4 a4 = *(const float4*)&As[k][ty*4];
            ull a;
            a=dup2(a4.x); fma2(acc[0][0],a,b0); fma2(acc[0][1],a,b1);
            a=dup2(a4.y); fma2(acc[1][0],a,b0); fma2(acc[1][1],a,b1);
            a=dup2(a4.z); fma2(acc[2][0],a,b0); fma2(acc[2][1],a,b1);
            a=dup2(a4.w); fma2(acc[3][0],a,b0); fma2(acc[3][1],a,b1);
        }
    }
#pragma unroll
    for (int i=0;i<4;++i){
        int row = bm + ty*4 + i;
        float2 c0=unp2(acc[i][0]), c1=unp2(acc[i][1]);
        float v[4]={c0.x,c0.y,c1.x,c1.y};
#pragma unroll
        for (int j=0;j<4;++j){
            int col = bn + tx*4 + j;
            if (col < N) C[(size_t)row*N + col] = v[j] + bias[col];
        }
    }
}

// =======================================================================
// A-pack prep: fp32 W -> gate-interleaved, SW128-preswizzled bf16 hi/lo
// =======================================================================
template<int L>
__global__ void prep_A(const float* __restrict__ Wi, const float* __restrict__ Wh)
{
    using C = LC<L>;
    size_t idx = (size_t)blockIdx.x*256 + threadIdx.x;
    size_t total = (size_t)C::NJB*C::NCH*8192;
    if (idx >= total) return;
    int kk  = (int)(idx & 63);
    int row = (int)((idx>>6) & 127);
    int ch  = (int)((idx>>13) % C::NCH);
    int jb  = (int)(idx / ((size_t)C::NCH*8192));
    int gate = row>>5, j = jb*32 + (row&31);
    int kabs = ch*64 + kk;
    float v = 0.f;
    if (j < C::OUT){
        if (kabs < C::KX)                 v = Wi[(size_t)(gate*C::OUT + j)*C::KX + kabs];
        else if (kabs < C::KX + C::KH)    v = Wh[(size_t)(gate*C::OUT + j)*C::KH + (kabs - C::KX)];
    }
    __nv_bfloat16 h = __float2bfloat16(v);
    __nv_bfloat16 l = __float2bfloat16(v - __bfloat162float(h));
    uint32_t pos = SWZ((uint32_t)(row*128 + kk*2)) >> 1;
    __nv_bfloat16* Ap = Apack<L>() + (size_t)(jb*C::NCH + ch)*16384;
    Ap[pos] = h;
    Ap[8192 + pos] = l;
}

// =======================================================================
// Fused layer step: MMA (m16n8k16 bf16, 3 split passes) + last-CTA-reduces
// pointwise. grid = NJB*S CTAs, 128 threads = 4 warps. Node count per step
// drops from 6 to 3 (keeps the graph-exec param pool inside its first
// chunk, which the R10 run showed is load-bearing for the harness rule).
// =======================================================================
#define STGB 40960
#define SMEM_MMA (4*STGB)

template<int L>
__global__ __launch_bounds__(128) void layer_step(
    const float* __restrict__ bx, const float* __restrict__ bhh, int t)
{
    using C = LC<L>;
    extern __shared__ __align__(128) char sm[];
    __shared__ int s_last;
    const int tid = threadIdx.x;
    const int w = tid >> 5, ln = tid & 31;
    const int jb = blockIdx.x / C::S, s = blockIdx.x % C::S;
    const int c0 = (s*C::NCH)/C::S, c1n = ((s+1)*C::NCH)/C::S, n = c1n - c0;
    const int par = t & 1;
    uint32_t sb = smem_u32(sm);
    const __nv_bfloat16* Ab = Apack<L>() + (size_t)(jb*C::NCH + c0)*16384;
    const __nv_bfloat16* Bb = Bpack<L>(par) + (size_t)c0*4096;

    auto fill = [&](int i){
        uint32_t dst = sb + (i & 3)*STGB;
        const char* a = (const char*)(Ab + (size_t)i*16384);
#pragma unroll
        for (int r=0;r<16;r++) cpa16(dst + r*2048 + tid*16, a + r*2048 + tid*16);
        const char* b = (const char*)(Bb + (size_t)i*4096);
#pragma unroll
        for (int r=0;r<4;r++) cpa16(dst + 32768 + r*2048 + tid*16, b + r*2048 + tid*16);
    };
    for (int i=0;i<4;i++){ if (i<n) fill(i); CPA_COMMIT(); }

    float acc[2][4][4];
#pragma unroll
    for (int mi=0;mi<2;mi++)
#pragma unroll
        for (int ni=0;ni<4;ni++)
#pragma unroll
            for (int q=0;q<4;q++) acc[mi][ni][q]=0.f;

    const int arow = w*32 + (ln&7) + ((ln>>3)&1)*8;   // + mi*16
    const int akad = ((ln>>4)&1)*16;
    const int brow = ((ln>>4)&1)*8 + (ln&7);
    const int bkad = ((ln>>3)&1)*16;

    for (int i=0;i<n;i++){
        asm volatile("cp.async.wait_group 3;" ::: "memory");
        __syncthreads();
        uint32_t so = sb + (i & 3)*STGB;
#pragma unroll
        for (int p=0;p<3;p++){
            uint32_t aoff = so + ((p==2)?16384u:0u);
            uint32_t boff = so + ((p==1)?36864u:32768u);
#pragma unroll
            for (int ks=0;ks<4;ks++){
                const int kb = ks*32;
                uint32_t bf[8];
                uint32_t ba0 = boff + SWZ((uint32_t)(brow*128 + kb + bkad));
                uint32_t ba1 = boff + SWZ((uint32_t)((brow+16)*128 + kb + bkad));
                asm volatile("ldmatrix.sync.aligned.m8n8.x4.shared.b16 {%0,%1,%2,%3}, [%4];"
                    : "=r"(bf[0]),"=r"(bf[1]),"=r"(bf[2]),"=r"(bf[3]) : "r"(ba0));
                asm volatile("ldmatrix.sync.aligned.m8n8.x4.shared.b16 {%0,%1,%2,%3}, [%4];"
                    : "=r"(bf[4]),"=r"(bf[5]),"=r"(bf[6]),"=r"(bf[7]) : "r"(ba1));
#pragma unroll
                for (int mi=0;mi<2;mi++){
                    uint32_t af[4];
                    uint32_t aa = aoff + SWZ((uint32_t)((arow+mi*16)*128 + kb + akad));
                    asm volatile("ldmatrix.sync.aligned.m8n8.x4.shared.b16 {%0,%1,%2,%3}, [%4];"
                        : "=r"(af[0]),"=r"(af[1]),"=r"(af[2]),"=r"(af[3]) : "r"(aa));
#pragma unroll
                    for (int ni=0;ni<4;ni++){
                        asm volatile(
                            "mma.sync.aligned.m16n8k16.row.col.f32.bf16.bf16.f32 "
                            "{%0,%1,%2,%3}, {%4,%5,%6,%7}, {%8,%9}, {%0,%1,%2,%3};"
                            : "+f"(acc[mi][ni][0]),"+f"(acc[mi][ni][1]),
                              "+f"(acc[mi][ni][2]),"+f"(acc[mi][ni][3])
                            : "r"(af[0]),"r"(af[1]),"r"(af[2]),"r"(af[3]),
                              "r"(bf[ni*2]),"r"(bf[ni*2+1]));
                    }
                }
            }
        }
        __syncthreads();
        if (i+4 < n) fill(i+4);
        CPA_COMMIT();
    }

    // write partials: P[row*32 + batch]
    float* P = Ppart<L>() + (size_t)blockIdx.x*4096;
#pragma unroll
    for (int mi=0;mi<2;mi++){
        int row = w*32 + mi*16 + (ln>>2);
#pragma unroll
        for (int ni=0;ni<4;ni++){
            int col = ni*8 + (ln&3)*2;
            *(float2*)(P + row*32 + col)     = make_float2(acc[mi][ni][0], acc[mi][ni][1]);
            *(float2*)(P + (row+8)*32 + col) = make_float2(acc[mi][ni][2], acc[mi][ni][3]);
        }
    }

    // ---- last-CTA-for-this-jb does the fused pointwise ----
    __threadfence();
    __syncthreads();
    if (tid == 0){
        int old = atomicAdd(&g_cnt[L][jb], 1);
        s_last = (old == C::S - 1);
        if (s_last) g_cnt[L][jb] = 0;     // reset for the next launch
    }
    __syncthreads();
    if (!s_last) return;
    __threadfence();                       // acquire producers' partials

    const float* Pb = Ppart<L>() + (size_t)jb*C::S*4096;
    float* cst = g_c[L];
#pragma unroll
    for (int it=0; it<8; ++it){
        int item = tid + it*128;
        int jj = item>>5, b = item&31;
        int j = jb*32 + jj;
        if (j >= C::OUT) continue;
        float pre[4];
#pragma unroll
        for (int g=0; g<4; ++g){
            float sum = 0.f;
            for (int s2=0; s2<C::S; ++s2)
                sum += Pb[(size_t)s2*4096 + (g*32+jj)*32 + b];
            pre[g] = sum;
        }
        float ip, fp, op, gp;
        if (L == 0){
            const float* p0 = g_P0 + (size_t)(t*32 + b)*M4H + j;
            ip = pre[0]+p0[0]     +bhh[j];
            fp = pre[1]+p0[HH]    +bhh[HH+j];
            op = pre[2]+p0[2*HH]  +bhh[2*HH+j];
            gp = pre[3]+p0[3*HH]  +bhh[3*HH+j];
        } else {
            ip = pre[0]+bx[j]          +bhh[j];
            fp = pre[1]+bx[C::OUT+j]   +bhh[C::OUT+j];
            op = pre[2]+bx[2*C::OUT+j] +bhh[2*C::OUT+j];
            gp = pre[3]+bx[3*C::OUT+j] +bhh[3*C::OUT+j];
        }
        float gi=1.f/(1.f+expf(-ip)), gf=1.f/(1.f+expf(-fp));
        float go=1.f/(1.f+expf(-op)), gg=tanhf(gp);
        float cn = gf*cst[j*32+b] + gi*gg;
        cst[j*32+b] = cn;
        float hv = go*tanhf(cn);
        g_hf[L][j*32+b] = hv;
        if (L == 0){
            stageB(gB0[par^1], j, b, hv);
            stageB(gB1[par],   j, b, hv);
        } else if (L == 1){
            stageB(gB1[par^1], 1150 + j, b, hv);
            stageB(gB2[par],   j, b, hv);
        } else {
            stageB(gB2[par^1], 1150 + j, b, hv);
            g_h2all[(size_t)(t*32 + b)*EE + j] = hv;
        }
    }
}

// ---- init: c states + seed B packs (parity 0) ----
__global__ void init_states(const float* __restrict__ h0,
                            const float* __restrict__ c0,
                            const float* __restrict__ h0l,
                            const float* __restrict__ c0l)
{
    int idx = blockIdx.x*blockDim.x + threadIdx.x;
    if (idx < HH*BB){
        int k = idx>>5, b = idx&31;
        g_c[0][idx] = c0[b*HH + k];
        g_c[1][idx] = c0[BB*HH + b*HH + k];
        stageB(gB0[0], k,        b, h0[b*HH + k]);
        stageB(gB1[0], 1150 + k, b, h0[BB*HH + b*HH + k]);
    }
    if (idx < EE*BB){
        int k = idx>>5, b = idx&31;
        g_c[2][idx] = c0l[b*EE + k];
        stageB(gB2[0], 1150 + k, b, h0l[b*EE + k]);
    }
}

__global__ void finalize_states(float* __restrict__ out)
{
    const size_t D1 = (size_t)TT*BB*VV;
    const size_t D2 = D1 + 2*BB*HH;
    const size_t D3 = D2 + BB*EE;
    const size_t D4 = D3 + 2*BB*HH;
    int idx = blockIdx.x*blockDim.x + threadIdx.x;
    if (idx < HH*BB){
        int k = idx>>5, b = idx&31;
        out[D1 + b*HH + k]           = g_hf[0][idx];
        out[D1 + BB*HH + b*HH + k]   = g_hf[1][idx];
        out[D3 + b*HH + k]           = g_c[0][idx];
        out[D3 + BB*HH + b*HH + k]   = g_c[1][idx];
    }
    if (idx < EE*BB){
        int k = idx>>5, b = idx&31;
        out[D2 + b*EE + k] = g_hf[2][idx];
        out[D4 + b*EE + k] = g_c[2][idx];
    }
}

// =======================================================================
extern "C" void kernel_launch(void* const* d_in, const int* in_sizes, int n_in,
                              void* d_out, int out_size)
{
    const int*   x    = (const int*)  d_in[0];
    const float* h0   = (const float*)d_in[1];
    const float* c0   = (const float*)d_in[2];
    const float* h0l  = (const float*)d_in[3];
    const float* c0l  = (const float*)d_in[4];
    const float* emb  = (const float*)d_in[5];
    const float* Wi0  = (const float*)d_in[6];
    const float* bi0  = (const float*)d_in[7];
    const float* Wh0  = (const float*)d_in[8];
    const float* bh0  = (const float*)d_in[9];
    const float* Wi1  = (const float*)d_in[10];
    const float* bi1  = (const float*)d_in[11];
    const float* Wh1  = (const float*)d_in[12];
    const float* bh1  = (const float*)d_in[13];
    const float* Wi2  = (const float*)d_in[14];
    const float* bi2  = (const float*)d_in[15];
    const float* Wh2  = (const float*)d_in[16];
    const float* bh2  = (const float*)d_in[17];
    const float* decW = (const float*)d_in[18];
    const float* decb = (const float*)d_in[19];
    float* out = (float*)d_out;

    cudaFuncSetAttribute(layer_step<0>, cudaFuncAttributeMaxDynamicSharedMemorySize, SMEM_MMA);
    cudaFuncSetAttribute(layer_step<1>, cudaFuncAttributeMaxDynamicSharedMemorySize, SMEM_MMA);
    cudaFuncSetAttribute(layer_step<2>, cudaFuncAttributeMaxDynamicSharedMemorySize, SMEM_MMA);

    init_states<<<(HH*BB + 255)/256, 256>>>(h0, c0, h0l, c0l);

    prep_A<0><<<(36*18*8192 + 255)/256, 256>>>(nullptr, Wh0);
    prep_A<1><<<(36*36*8192 + 255)/256, 256>>>(Wi1, Wh1);
    prep_A<2><<<(13*25*8192 + 255)/256, 256>>>(Wi2, Wh2);

    {   // P0 = emb[x] @ Wi0^T + bi0
        dim3 g((M4H + 63)/64, NROW/64);
        sgemm_nt<0><<<g, 256>>>(emb, x, Wi0, bi0, nullptr, M4H);
    }

    for (int t = 0; t < TT; ++t){
        layer_step<0><<<36*4, 128, SMEM_MMA>>>(bh0, bh0, t);
        layer_step<1><<<36*4, 128, SMEM_MMA>>>(bi1, bh1, t);
        layer_step<2><<<13*8, 128, SMEM_MMA>>>(bi2, bh2, t);
    }

    {   // decoder
        dim3 g((VV + 63)/64, NROW/64);
        sgemm_nt<1><<<g, 256>>>(nullptr, nullptr, decW, decb, out, VV);
    }

    finalize_states<<<(HH*BB + 255)/256, 256>>>(out);
}

// round 13
// speedup vs baseline: 1.0215x; 1.0215x over previous
#include <cuda_runtime.h>
#include <cuda_bf16.h>
#include <math.h>
#include <stdint.h>

#define EE   400
#define HH   1150
#define VV   10000
#define TT   256
#define BB   32
#define M4H  4600
#define NROW 8192
#define NCTA 144
typedef unsigned long long ull;

template<int L> struct LC;
template<> struct LC<0>{ enum{OUT=1150,NJB=36,NCH=18,S=4,KX=0,   KH=1150}; };
template<> struct LC<1>{ enum{OUT=1150,NJB=36,NCH=36,S=4,KX=1150,KH=1150}; };
template<> struct LC<2>{ enum{OUT=400, NJB=13,NCH=25,S=8,KX=1150,KH=400 }; };

// ---------------- device scratch ----------------
__device__ __align__(16) float g_P0[(size_t)NROW * M4H];
__device__ __align__(16) float g_h2all[(size_t)NROW * EE];
__device__ __align__(16) float g_c[3][HH * BB];
__device__ __align__(16) float g_hf[3][HH * BB];
__device__ __align__(16) __nv_bfloat16 gA0[(size_t)36*18*16384];
__device__ __align__(16) __nv_bfloat16 gA1[(size_t)36*36*16384];
__device__ __align__(16) __nv_bfloat16 gA2[(size_t)13*25*16384];
__device__ __align__(16) __nv_bfloat16 gB0[2][18*4096];
__device__ __align__(16) __nv_bfloat16 gB1[2][36*4096];
__device__ __align__(16) __nv_bfloat16 gB2[2][25*4096];
__device__ __align__(16) float gPart0[36*4*4096];
__device__ __align__(16) float gPart1[36*4*4096];
__device__ __align__(16) float gPart2[13*8*4096];
__device__ int g_cnt[3][36];      // zero-init; consumer resets via atomicExch
__device__ int g_barslot[512];    // zero-init; slot i-1 reset by slot i's last arriver

template<int L> __device__ __forceinline__ __nv_bfloat16* Apack(){
    return (L==0) ? gA0 : (L==1) ? gA1 : gA2;
}
template<int L> __device__ __forceinline__ __nv_bfloat16* Bpack(int par){
    return (L==0) ? gB0[par] : (L==1) ? gB1[par] : gB2[par];
}
template<int L> __device__ __forceinline__ float* Ppart(){
    return (L==0) ? gPart0 : (L==1) ? gPart1 : gPart2;
}

// ---------------- helpers ----------------
#define SWZ(x) ((x) ^ (((x) >> 3) & 0x70))
__device__ __forceinline__ uint32_t smem_u32(const void* p){
    uint32_t a;
    asm("{ .reg .u64 t; cvta.to.shared.u64 t, %1; cvt.u32.u64 %0, t; }" : "=r"(a) : "l"(p));
    return a;
}
__device__ __forceinline__ void cpa16(uint32_t dst, const void* src){
    asm volatile("cp.async.ca.shared.global [%0], [%1], 16;" :: "r"(dst), "l"(src));
}
#define CPA_COMMIT() asm volatile("cp.async.commit_group;" ::: "memory")

__device__ __forceinline__ void stageB(__nv_bfloat16* base, int kabs, int b, float v){
    int c = kabs >> 6, kk = kabs & 63;
    uint32_t pos = SWZ((uint32_t)(b*128 + kk*2)) >> 1;
    __nv_bfloat16 h = __float2bfloat16(v);
    base[(size_t)c*4096 + pos]        = h;
    base[(size_t)c*4096 + 2048 + pos] = __float2bfloat16(v - __bfloat162float(h));
}

__device__ __forceinline__ void fma2(ull& d, ull a, ull b){
    asm("fma.rn.f32x2 %0, %1, %2, %0;" : "+l"(d) : "l"(a), "l"(b));
}
__device__ __forceinline__ ull dup2(float x){
    ull r; asm("mov.b64 %0, {%1, %2};" : "=l"(r) : "f"(x), "f"(x)); return r;
}
__device__ __forceinline__ float2 unp2(ull v){
    float2 r; asm("mov.b64 {%0, %1}, %2;" : "=f"(r.x), "=f"(r.y) : "l"(v)); return r;
}

// =======================================================================
// fp32 SGEMM (proven)
// =======================================================================
template<int MODE>
__global__ __launch_bounds__(256) void sgemm_nt(
    const float* __restrict__ A, const int* __restrict__ gidx,
    const float* __restrict__ Bm, const float* __restrict__ bias,
    float* __restrict__ Cout, int N)
{
    const int K = EE;
    __shared__ __align__(16) float As[16][68];
    __shared__ __align__(16) float Bs[16][68];
    float* C = (MODE==0) ? g_P0 : Cout;
    const float* Abase = (MODE==1) ? g_h2all : A;
    const int tid = threadIdx.x;
    const int bm = blockIdx.y*64, bn = blockIdx.x*64;
    const int r = tid>>2, q = tid&3;
    const float* arow = (MODE==0) ? Abase + (size_t)gidx[bm+r]*K : Abase + (size_t)(bm+r)*K;
    const int nrow = bn + r;
    const bool bok = nrow < N;
    const float* brow = Bm + (size_t)(bok ? nrow : (N-1))*K;
    const int tx = tid&15, ty = tid>>4;
    ull acc[4][2];
#pragma unroll
    for (int i=0;i<4;++i){ acc[i][0]=0ull; acc[i][1]=0ull; }
    for (int kc=0;kc<K;kc+=16){
        float4 av = *(const float4*)(arow + kc + q*4);
        float4 bv = *(const float4*)(brow + kc + q*4);
        if (!bok){ bv.x=bv.y=bv.z=bv.w=0.f; }
        __syncthreads();
        As[q*4+0][r]=av.x; As[q*4+1][r]=av.y; As[q*4+2][r]=av.z; As[q*4+3][r]=av.w;
        Bs[q*4+0][r]=bv.x; Bs[q*4+1][r]=bv.y; Bs[q*4+2][r]=bv.z; Bs[q*4+3][r]=bv.w;
        __syncthreads();
#pragma unroll
        for (int k=0;k<16;++k){
            ull b0 = *(const ull*)&Bs[k][tx*4];
            ull b1 = *(const ull*)&Bs[k][tx*4+2];
            float4 a4 = *(const float4*)&As[k][ty*4];
            ull a;
            a=dup2(a4.x); fma2(acc[0][0],a,b0); fma2(acc[0][1],a,b1);
            a=dup2(a4.y); fma2(acc[1][0],a,b0); fma2(acc[1][1],a,b1);
            a=dup2(a4.z); fma2(acc[2][0],a,b0); fma2(acc[2][1],a,b1);
            a=dup2(a4.w); fma2(acc[3][0],a,b0); fma2(acc[3][1],a,b1);
        }
    }
#pragma unroll
    for (int i=0;i<4;++i){
        int row = bm + ty*4 + i;
        float2 c0=unp2(acc[i][0]), c1=unp2(acc[i][1]);
        float v[4]={c0.x,c0.y,c1.x,c1.y};
#pragma unroll
        for (int j=0;j<4;++j){
            int col = bn + tx*4 + j;
            if (col < N) C[(size_t)row*N + col] = v[j] + bias[col];
        }
    }
}

// =======================================================================
// A-pack prep (unchanged)
// =======================================================================
template<int L>
__global__ void prep_A(const float* __restrict__ Wi, const float* __restrict__ Wh)
{
    using C = LC<L>;
    size_t idx = (size_t)blockIdx.x*256 + threadIdx.x;
    size_t total = (size_t)C::NJB*C::NCH*8192;
    if (idx >= total) return;
    int kk  = (int)(idx & 63);
    int row = (int)((idx>>6) & 127);
    int ch  = (int)((idx>>13) % C::NCH);
    int jb  = (int)(idx / ((size_t)C::NCH*8192));
    int gate = row>>5, j = jb*32 + (row&31);
    int kabs = ch*64 + kk;
    float v = 0.f;
    if (j < C::OUT){
        if (kabs < C::KX)                 v = Wi[(size_t)(gate*C::OUT + j)*C::KX + kabs];
        else if (kabs < C::KX + C::KH)    v = Wh[(size_t)(gate*C::OUT + j)*C::KH + (kabs - C::KX)];
    }
    __nv_bfloat16 h = __float2bfloat16(v);
    __nv_bfloat16 l = __float2bfloat16(v - __bfloat162float(h));
    uint32_t pos = SWZ((uint32_t)(row*128 + kk*2)) >> 1;
    __nv_bfloat16* Ap = Apack<L>() + (size_t)(jb*C::NCH + ch)*16384;
    Ap[pos] = h;
    Ap[8192 + pos] = l;
}

// =======================================================================
// Persistent recurrence: 1 kernel, 256 steps x 3 phases, grid barriers.
// =======================================================================
#define STGB 40960
#define SMEM_MMA (4*STGB)

__device__ __forceinline__ void gridbar(int slot){
    __syncthreads();
    if (threadIdx.x == 0){
        __threadfence();
        int old = atomicAdd(&g_barslot[slot], 1);
        if (old == NCTA-1 && slot > 0)
            atomicExch(&g_barslot[slot-1], 0);
        while (atomicAdd(&g_barslot[slot], 0) < NCTA) __nanosleep(32);
        __threadfence();
    }
    __syncthreads();
}

template<int L>
__device__ __forceinline__ void do_layer(
    char* sm, const float* __restrict__ bx, const float* __restrict__ bhh, int t)
{
    using C = LC<L>;
    __shared__ int s_last;
    const int blk = blockIdx.x;
    if (L == 2 && blk >= C::NJB * C::S) return;
    const int tid = threadIdx.x;
    const int w = tid >> 5, ln = tid & 31;
    const int jb = blk / C::S, s = blk % C::S;
    const int c0 = (s*C::NCH)/C::S, c1n = ((s+1)*C::NCH)/C::S, n = c1n - c0;
    const int par = t & 1;
    uint32_t sb = smem_u32(sm);
    const __nv_bfloat16* Ab = Apack<L>() + (size_t)(jb*C::NCH + c0)*16384;
    const __nv_bfloat16* Bb = Bpack<L>(par) + (size_t)c0*4096;

    auto fill = [&](int i){
        uint32_t dst = sb + (i & 3)*STGB;
        const char* a = (const char*)(Ab + (size_t)i*16384);
#pragma unroll
        for (int r=0;r<16;r++) cpa16(dst + r*2048 + tid*16, a + r*2048 + tid*16);
        const char* b = (const char*)(Bb + (size_t)i*4096);
#pragma unroll
        for (int r=0;r<4;r++) cpa16(dst + 32768 + r*2048 + tid*16, b + r*2048 + tid*16);
    };
    for (int i=0;i<4;i++){ if (i<n) fill(i); CPA_COMMIT(); }

    float acc[2][4][4];
#pragma unroll
    for (int mi=0;mi<2;mi++)
#pragma unroll
        for (int ni=0;ni<4;ni++)
#pragma unroll
            for (int q=0;q<4;q++) acc[mi][ni][q]=0.f;

    const int arow = w*32 + (ln&7) + ((ln>>3)&1)*8;
    const int akad = ((ln>>4)&1)*16;
    const int brow = ((ln>>4)&1)*8 + (ln&7);
    const int bkad = ((ln>>3)&1)*16;

    for (int i=0;i<n;i++){
        asm volatile("cp.async.wait_group 3;" ::: "memory");
        __syncthreads();
        uint32_t so = sb + (i & 3)*STGB;
#pragma unroll
        for (int p=0;p<3;p++){
            uint32_t aoff = so + ((p==2)?16384u:0u);
            uint32_t boff = so + ((p==1)?36864u:32768u);
#pragma unroll
            for (int ks=0;ks<4;ks++){
                const int kb = ks*32;
                uint32_t bf[8];
                uint32_t ba0 = boff + SWZ((uint32_t)(brow*128 + kb + bkad));
                uint32_t ba1 = boff + SWZ((uint32_t)((brow+16)*128 + kb + bkad));
                asm volatile("ldmatrix.sync.aligned.m8n8.x4.shared.b16 {%0,%1,%2,%3}, [%4];"
                    : "=r"(bf[0]),"=r"(bf[1]),"=r"(bf[2]),"=r"(bf[3]) : "r"(ba0));
                asm volatile("ldmatrix.sync.aligned.m8n8.x4.shared.b16 {%0,%1,%2,%3}, [%4];"
                    : "=r"(bf[4]),"=r"(bf[5]),"=r"(bf[6]),"=r"(bf[7]) : "r"(ba1));
#pragma unroll
                for (int mi=0;mi<2;mi++){
                    uint32_t af[4];
                    uint32_t aa = aoff + SWZ((uint32_t)((arow+mi*16)*128 + kb + akad));
                    asm volatile("ldmatrix.sync.aligned.m8n8.x4.shared.b16 {%0,%1,%2,%3}, [%4];"
                        : "=r"(af[0]),"=r"(af[1]),"=r"(af[2]),"=r"(af[3]) : "r"(aa));
#pragma unroll
                    for (int ni=0;ni<4;ni++){
                        asm volatile(
                            "mma.sync.aligned.m16n8k16.row.col.f32.bf16.bf16.f32 "
                            "{%0,%1,%2,%3}, {%4,%5,%6,%7}, {%8,%9}, {%0,%1,%2,%3};"
                            : "+f"(acc[mi][ni][0]),"+f"(acc[mi][ni][1]),
                              "+f"(acc[mi][ni][2]),"+f"(acc[mi][ni][3])
                            : "r"(af[0]),"r"(af[1]),"r"(af[2]),"r"(af[3]),
                              "r"(bf[ni*2]),"r"(bf[ni*2+1]));
                    }
                }
            }
        }
        __syncthreads();
        if (i+4 < n) fill(i+4);
        CPA_COMMIT();
    }

    float* P = Ppart<L>() + (size_t)blk*4096;
#pragma unroll
    for (int mi=0;mi<2;mi++){
        int row = w*32 + mi*16 + (ln>>2);
#pragma unroll
        for (int ni=0;ni<4;ni++){
            int col = ni*8 + (ln&3)*2;
            *(float2*)(P + row*32 + col)     = make_float2(acc[mi][ni][0], acc[mi][ni][1]);
            *(float2*)(P + (row+8)*32 + col) = make_float2(acc[mi][ni][2], acc[mi][ni][3]);
        }
    }

    __threadfence();
    __syncthreads();
    if (tid == 0){
        int old = atomicAdd(&g_cnt[L][jb], 1);
        s_last = (old == C::S - 1);
        if (s_last) atomicExch(&g_cnt[L][jb], 0);
    }
    __syncthreads();
    if (!s_last) return;
    __threadfence();

    const float* Pb = Ppart<L>() + (size_t)jb*C::S*4096;
    float* cst = g_c[L];
#pragma unroll
    for (int it=0; it<8; ++it){
        int item = tid + it*128;
        int jj = item>>5, b = item&31;
        int j = jb*32 + jj;
        if (j >= C::OUT) continue;
        float pre[4];
#pragma unroll
        for (int g=0; g<4; ++g){
            float sum = 0.f;
            for (int s2=0; s2<C::S; ++s2)
                sum += Pb[(size_t)s2*4096 + (g*32+jj)*32 + b];
            pre[g] = sum;
        }
        float ip, fp, op, gp;
        if (L == 0){
            const float* p0 = g_P0 + (size_t)(t*32 + b)*M4H + j;
            ip = pre[0]+p0[0]     +bhh[j];
            fp = pre[1]+p0[HH]    +bhh[HH+j];
            op = pre[2]+p0[2*HH]  +bhh[2*HH+j];
            gp = pre[3]+p0[3*HH]  +bhh[3*HH+j];
        } else {
            ip = pre[0]+bx[j]          +bhh[j];
            fp = pre[1]+bx[C::OUT+j]   +bhh[C::OUT+j];
            op = pre[2]+bx[2*C::OUT+j] +bhh[2*C::OUT+j];
            gp = pre[3]+bx[3*C::OUT+j] +bhh[3*C::OUT+j];
        }
        float gi=1.f/(1.f+expf(-ip)), gf=1.f/(1.f+expf(-fp));
        float go=1.f/(1.f+expf(-op)), gg=tanhf(gp);
        float cn = gf*cst[j*32+b] + gi*gg;
        cst[j*32+b] = cn;
        float hv = go*tanhf(cn);
        g_hf[L][j*32+b] = hv;
        if (L == 0){
            stageB(gB0[par^1], j, b, hv);
            stageB(gB1[par],   j, b, hv);
        } else if (L == 1){
            stageB(gB1[par^1], 1150 + j, b, hv);
            stageB(gB2[par],   j, b, hv);
        } else {
            stageB(gB2[par^1], 1150 + j, b, hv);
            g_h2all[(size_t)(t*32 + b)*EE + j] = hv;
        }
    }
}

__global__ __launch_bounds__(128) void recurrence(
    const float* __restrict__ bh0,
    const float* __restrict__ bi1, const float* __restrict__ bh1,
    const float* __restrict__ bi2, const float* __restrict__ bh2)
{
    extern __shared__ __align__(128) char sm[];
    // replay-safe reset of the final barrier slot (causally ordered: every
    // arrival at slot 511 requires CTA0 to have passed 511 earlier barriers)
    if (blockIdx.x == 0 && threadIdx.x == 0)
        atomicExch(&g_barslot[511], 0);
    int slot = 0;
    for (int t = 0; t < TT; ++t){
        do_layer<0>(sm, bh0, bh0, t);
        gridbar(slot++);
        do_layer<1>(sm, bi1, bh1, t);
        gridbar(slot++);
        do_layer<2>(sm, bi2, bh2, t);
        // no barrier: L2(t) shares nothing with L0/L1(t+1); all other
        // cross-step hazards are >=2 barriers apart.
    }
}

// ---- init / finalize (unchanged) ----
__global__ void init_states(const float* __restrict__ h0,
                            const float* __restrict__ c0,
                            const float* __restrict__ h0l,
                            const float* __restrict__ c0l)
{
    int idx = blockIdx.x*blockDim.x + threadIdx.x;
    if (idx < HH*BB){
        int k = idx>>5, b = idx&31;
        g_c[0][idx] = c0[b*HH + k];
        g_c[1][idx] = c0[BB*HH + b*HH + k];
        stageB(gB0[0], k,        b, h0[b*HH + k]);
        stageB(gB1[0], 1150 + k, b, h0[BB*HH + b*HH + k]);
    }
    if (idx < EE*BB){
        int k = idx>>5, b = idx&31;
        g_c[2][idx] = c0l[b*EE + k];
        stageB(gB2[0], 1150 + k, b, h0l[b*EE + k]);
    }
}

__global__ void finalize_states(float* __restrict__ out)
{
    const size_t D1 = (size_t)TT*BB*VV;
    const size_t D2 = D1 + 2*BB*HH;
    const size_t D3 = D2 + BB*EE;
    const size_t D4 = D3 + 2*BB*HH;
    int idx = blockIdx.x*blockDim.x + threadIdx.x;
    if (idx < HH*BB){
        int k = idx>>5, b = idx&31;
        out[D1 + b*HH + k]           = g_hf[0][idx];
        out[D1 + BB*HH + b*HH + k]   = g_hf[1][idx];
        out[D3 + b*HH + k]           = g_c[0][idx];
        out[D3 + BB*HH + b*HH + k]   = g_c[1][idx];
    }
    if (idx < EE*BB){
        int k = idx>>5, b = idx&31;
        out[D2 + b*EE + k] = g_hf[2][idx];
        out[D4 + b*EE + k] = g_c[2][idx];
    }
}

// =======================================================================
extern "C" void kernel_launch(void* const* d_in, const int* in_sizes, int n_in,
                              void* d_out, int out_size)
{
    const int*   x    = (const int*)  d_in[0];
    const float* h0   = (const float*)d_in[1];
    const float* c0   = (const float*)d_in[2];
    const float* h0l  = (const float*)d_in[3];
    const float* c0l  = (const float*)d_in[4];
    const float* emb  = (const float*)d_in[5];
    const float* Wi0  = (const float*)d_in[6];
    const float* bi0  = (const float*)d_in[7];
    const float* Wh0  = (const float*)d_in[8];
    const float* bh0  = (const float*)d_in[9];
    const float* Wi1  = (const float*)d_in[10];
    const float* bi1  = (const float*)d_in[11];
    const float* Wh1  = (const float*)d_in[12];
    const float* bh1  = (const float*)d_in[13];
    const float* Wi2  = (const float*)d_in[14];
    const float* bi2  = (const float*)d_in[15];
    const float* Wh2  = (const float*)d_in[16];
    const float* bh2  = (const float*)d_in[17];
    const float* decW = (const float*)d_in[18];
    const float* decb = (const float*)d_in[19];
    float* out = (float*)d_out;

    cudaFuncSetAttribute(recurrence, cudaFuncAttributeMaxDynamicSharedMemorySize, SMEM_MMA);

    init_states<<<(HH*BB + 255)/256, 256>>>(h0, c0, h0l, c0l);

    prep_A<0><<<(36*18*8192 + 255)/256, 256>>>(nullptr, Wh0);
    prep_A<1><<<(36*36*8192 + 255)/256, 256>>>(Wi1, Wh1);
    prep_A<2><<<(13*25*8192 + 255)/256, 256>>>(Wi2, Wh2);

    {   // P0 = emb[x] @ Wi0^T + bi0
        dim3 g((M4H + 63)/64, NROW/64);
        sgemm_nt<0><<<g, 256>>>(emb, x, Wi0, bi0, nullptr, M4H);
    }

    recurrence<<<NCTA, 128, SMEM_MMA>>>(bh0, bi1, bh1, bi2, bh2);

    {   // decoder
        dim3 g((VV + 63)/64, NROW/64);
        sgemm_nt<1><<<g, 256>>>(nullptr, nullptr, decW, decb, out, VV);
    }

    finalize_states<<<(HH*BB + 255)/256, 256>>>(out);
}

// round 14
// speedup vs baseline: 1.7084x; 1.6724x over previous
#include <cuda_runtime.h>
#include <cuda_bf16.h>
#include <math.h>
#include <stdint.h>

#define EE   400
#define HH   1150
#define VV   10000
#define TT   256
#define BB   32
#define M4H  4600
#define NROW 8192
#define NCTA 144
typedef unsigned long long ull;

// K layouts padded so KX is a multiple of 8/64: KXP=1152
template<int L> struct LC;
template<> struct LC<0>{ enum{OUT=1150,NJB=36,NCH=18,S=4,KXP=0,   KH=1150}; };
template<> struct LC<1>{ enum{OUT=1150,NJB=36,NCH=36,S=4,KXP=1152,KH=1150}; };
template<> struct LC<2>{ enum{OUT=400, NJB=13,NCH=25,S=8,KXP=1152,KH=400 }; };

// ---------------- device scratch ----------------
__device__ __align__(16) float g_P0[(size_t)NROW * M4H];   // TRANSPOSED: [t][4600][b]
__device__ __align__(16) float g_h2all[(size_t)NROW * EE];
__device__ __align__(16) float g_c[3][HH * BB];
__device__ __align__(16) float g_hf[3][HH * BB];
__device__ __align__(16) __nv_bfloat16 gA0[(size_t)36*18*16384];
__device__ __align__(16) __nv_bfloat16 gA1[(size_t)36*36*16384];
__device__ __align__(16) __nv_bfloat16 gA2[(size_t)13*25*16384];
__device__ __align__(16) __nv_bfloat16 gB0[2][18*4096];
__device__ __align__(16) __nv_bfloat16 gB1[2][36*4096];
__device__ __align__(16) __nv_bfloat16 gB2[2][25*4096];
__device__ __align__(16) float gPart0[36*4*4096];
__device__ __align__(16) float gPart1[36*4*4096];
__device__ __align__(16) float gPart2[13*8*4096];
__device__ int g_cnt[3][36];      // monotonic within a launch; reset at kernel start
__device__ int g_barslot[513];    // slot i-1 reset by slot i's last arriver; 512 at start

template<int L> __device__ __forceinline__ __nv_bfloat16* Apack(){
    return (L==0) ? gA0 : (L==1) ? gA1 : gA2;
}
template<int L> __device__ __forceinline__ __nv_bfloat16* Bpack(int par){
    return (L==0) ? gB0[par] : (L==1) ? gB1[par] : gB2[par];
}
template<int L> __device__ __forceinline__ float* Ppart(){
    return (L==0) ? gPart0 : (L==1) ? gPart1 : gPart2;
}

// ---------------- helpers ----------------
#define SWZ(x) ((x) ^ (((x) >> 3) & 0x70))
__device__ __forceinline__ uint32_t smem_u32(const void* p){
    uint32_t a;
    asm("{ .reg .u64 t; cvta.to.shared.u64 t, %1; cvt.u32.u64 %0, t; }" : "=r"(a) : "l"(p));
    return a;
}
__device__ __forceinline__ void cpa16(uint32_t dst, const void* src){
    asm volatile("cp.async.ca.shared.global [%0], [%1], 16;" :: "r"(dst), "l"(src));
}
#define CPA_COMMIT() asm volatile("cp.async.commit_group;" ::: "memory")

__device__ __forceinline__ int ld_acq(const int* p){
    int v; asm volatile("ld.acquire.gpu.b32 %0, [%1];" : "=r"(v) : "l"(p) : "memory");
    return v;
}

// element-wise staging (init only)
__device__ __forceinline__ void stageB(__nv_bfloat16* base, int kabs, int b, float v){
    int c = kabs >> 6, kk = kabs & 63;
    uint32_t pos = SWZ((uint32_t)(b*128 + kk*2)) >> 1;
    __nv_bfloat16 h = __float2bfloat16(v);
    base[(size_t)c*4096 + pos]        = h;
    base[(size_t)c*4096 + 2048 + pos] = __float2bfloat16(v - __bfloat162float(h));
}

__device__ __forceinline__ void fma2(ull& d, ull a, ull b){
    asm("fma.rn.f32x2 %0, %1, %2, %0;" : "+l"(d) : "l"(a), "l"(b));
}
__device__ __forceinline__ ull dup2(float x){
    ull r; asm("mov.b64 %0, {%1, %2};" : "=l"(r) : "f"(x), "f"(x)); return r;
}
__device__ __forceinline__ float2 unp2(ull v){
    float2 r; asm("mov.b64 {%0, %1}, %2;" : "=f"(r.x), "=f"(r.y) : "l"(v)); return r;
}
__device__ __forceinline__ uint32_t pkbf(__nv_bfloat16 a, __nv_bfloat16 b){
    return (uint32_t)__bfloat16_as_ushort(a) | ((uint32_t)__bfloat16_as_ushort(b) << 16);
}

// =======================================================================
// fp32 SGEMM. MODE 0: gather + bias, writes TRANSPOSED g_P0 [t][col][b].
// MODE 1: decoder, normal row-major output.
// =======================================================================
template<int MODE>
__global__ __launch_bounds__(256) void sgemm_nt(
    const float* __restrict__ A, const int* __restrict__ gidx,
    const float* __restrict__ Bm, const float* __restrict__ bias,
    float* __restrict__ Cout, int N)
{
    const int K = EE;
    __shared__ __align__(16) float As[16][68];
    __shared__ __align__(16) float Bs[16][68];
    const float* Abase = (MODE==1) ? g_h2all : A;
    const int tid = threadIdx.x;
    const int bm = blockIdx.y*64, bn = blockIdx.x*64;
    const int r = tid>>2, q = tid&3;
    const float* arow = (MODE==0) ? Abase + (size_t)gidx[bm+r]*K : Abase + (size_t)(bm+r)*K;
    const int nrow = bn + r;
    const bool bok = nrow < N;
    const float* brow = Bm + (size_t)(bok ? nrow : (N-1))*K;
    const int tx = tid&15, ty = tid>>4;
    ull acc[4][2];
#pragma unroll
    for (int i=0;i<4;++i){ acc[i][0]=0ull; acc[i][1]=0ull; }
    for (int kc=0;kc<K;kc+=16){
        float4 av = *(const float4*)(arow + kc + q*4);
        float4 bv = *(const float4*)(brow + kc + q*4);
        if (!bok){ bv.x=bv.y=bv.z=bv.w=0.f; }
        __syncthreads();
        As[q*4+0][r]=av.x; As[q*4+1][r]=av.y; As[q*4+2][r]=av.z; As[q*4+3][r]=av.w;
        Bs[q*4+0][r]=bv.x; Bs[q*4+1][r]=bv.y; Bs[q*4+2][r]=bv.z; Bs[q*4+3][r]=bv.w;
        __syncthreads();
#pragma unroll
        for (int k=0;k<16;++k){
            ull b0 = *(const ull*)&Bs[k][tx*4];
            ull b1 = *(const ull*)&Bs[k][tx*4+2];
            float4 a4 = *(const float4*)&As[k][ty*4];
            ull a;
            a=dup2(a4.x); fma2(acc[0][0],a,b0); fma2(acc[0][1],a,b1);
            a=dup2(a4.y); fma2(acc[1][0],a,b0); fma2(acc[1][1],a,b1);
            a=dup2(a4.z); fma2(acc[2][0],a,b0); fma2(acc[2][1],a,b1);
            a=dup2(a4.w); fma2(acc[3][0],a,b0); fma2(acc[3][1],a,b1);
        }
    }
    if constexpr (MODE == 0){
        __shared__ float Ts[64][65];
        __syncthreads();
#pragma unroll
        for (int i=0;i<4;++i){
            float2 c0=unp2(acc[i][0]), c1=unp2(acc[i][1]);
            float v[4]={c0.x,c0.y,c1.x,c1.y};
#pragma unroll
            for (int j=0;j<4;++j){
                int col = bn + tx*4 + j;
                Ts[ty*4+i][tx*4+j] = v[j] + (col < N ? bias[col] : 0.f);
            }
        }
        __syncthreads();
        for (int idx=tid; idx<4096; idx+=256){
            int cl = idx>>6, rl = idx&63;
            int col = bn + cl;
            if (col < N){
                int row = bm + rl;
                int t = row>>5, b = row&31;
                g_P0[((size_t)t*M4H + col)*32 + b] = Ts[rl][cl];
            }
        }
    } else {
#pragma unroll
        for (int i=0;i<4;++i){
            int row = bm + ty*4 + i;
            float2 c0=unp2(acc[i][0]), c1=unp2(acc[i][1]);
            float v[4]={c0.x,c0.y,c1.x,c1.y};
#pragma unroll
            for (int j=0;j<4;++j){
                int col = bn + tx*4 + j;
                if (col < N) Cout[(size_t)row*N + col] = v[j] + bias[col];
            }
        }
    }
}

// =======================================================================
// A-pack prep with KXP padding
// =======================================================================
template<int L>
__global__ void prep_A(const float* __restrict__ Wi, const float* __restrict__ Wh)
{
    using C = LC<L>;
    size_t idx = (size_t)blockIdx.x*256 + threadIdx.x;
    size_t total = (size_t)C::NJB*C::NCH*8192;
    if (idx >= total) return;
    int kk  = (int)(idx & 63);
    int row = (int)((idx>>6) & 127);
    int ch  = (int)((idx>>13) % C::NCH);
    int jb  = (int)(idx / ((size_t)C::NCH*8192));
    int gate = row>>5, j = jb*32 + (row&31);
    int kabs = ch*64 + kk;
    float v = 0.f;
    if (j < C::OUT){
        if (L != 0 && kabs < 1150)
            v = Wi[(size_t)(gate*C::OUT + j)*1150 + kabs];
        else if (kabs >= C::KXP && kabs - C::KXP < C::KH)
            v = Wh[(size_t)(gate*C::OUT + j)*C::KH + (kabs - C::KXP)];
    }
    __nv_bfloat16 h = __float2bfloat16(v);
    __nv_bfloat16 l = __float2bfloat16(v - __bfloat162float(h));
    uint32_t pos = SWZ((uint32_t)(row*128 + kk*2)) >> 1;
    __nv_bfloat16* Ap = Apack<L>() + (size_t)(jb*C::NCH + ch)*16384;
    Ap[pos] = h;
    Ap[8192 + pos] = l;
}

// =======================================================================
// Persistent recurrence
// =======================================================================
#define STGB 40960
#define SMEM_MMA (4*STGB)

__device__ __forceinline__ void gridbar(int slot){
    __syncthreads();
    if (threadIdx.x == 0){
        __threadfence();
        int old = atomicAdd(&g_barslot[slot], 1);
        if (old == NCTA-1 && slot > 0)
            atomicExch(&g_barslot[slot-1], 0);
        while (ld_acq(&g_barslot[slot]) < NCTA) __nanosleep(32);
    }
    __syncthreads();
}

template<int L>
__device__ __forceinline__ void do_layer(
    char* sm, const float* __restrict__ bx, const float* __restrict__ bhh, int t)
{
    using C = LC<L>;
    const int blk = blockIdx.x;
    if (L == 2 && blk >= C::NJB * C::S) return;
    const int tid = threadIdx.x;
    const int w = tid >> 5, ln = tid & 31;
    const int jb = blk / C::S, s = blk % C::S;
    const int c0 = (s*C::NCH)/C::S, c1n = ((s+1)*C::NCH)/C::S, n = c1n - c0;
    const int par = t & 1;
    uint32_t sb = smem_u32(sm);
    const __nv_bfloat16* Ab = Apack<L>() + (size_t)(jb*C::NCH + c0)*16384;
    const __nv_bfloat16* Bb = Bpack<L>(par) + (size_t)c0*4096;

    auto fill = [&](int i){
        uint32_t dst = sb + (i & 3)*STGB;
        const char* a = (const char*)(Ab + (size_t)i*16384);
#pragma unroll
        for (int r=0;r<16;r++) cpa16(dst + r*2048 + tid*16, a + r*2048 + tid*16);
        const char* b = (const char*)(Bb + (size_t)i*4096);
#pragma unroll
        for (int r=0;r<4;r++) cpa16(dst + 32768 + r*2048 + tid*16, b + r*2048 + tid*16);
    };
    for (int i=0;i<4;i++){ if (i<n) fill(i); CPA_COMMIT(); }

    float acc[2][4][4];
#pragma unroll
    for (int mi=0;mi<2;mi++)
#pragma unroll
        for (int ni=0;ni<4;ni++)
#pragma unroll
            for (int q=0;q<4;q++) acc[mi][ni][q]=0.f;

    const int arow = w*32 + (ln&7) + ((ln>>3)&1)*8;
    const int akad = ((ln>>4)&1)*16;
    const int brow = ((ln>>4)&1)*8 + (ln&7);
    const int bkad = ((ln>>3)&1)*16;

    for (int i=0;i<n;i++){
        asm volatile("cp.async.wait_group 3;" ::: "memory");
        __syncthreads();
        uint32_t so = sb + (i & 3)*STGB;
#pragma unroll
        for (int p=0;p<3;p++){
            uint32_t aoff = so + ((p==2)?16384u:0u);
            uint32_t boff = so + ((p==1)?36864u:32768u);
#pragma unroll
            for (int ks=0;ks<4;ks++){
                const int kb = ks*32;
                uint32_t bf[8];
                uint32_t ba0 = boff + SWZ((uint32_t)(brow*128 + kb + bkad));
                uint32_t ba1 = boff + SWZ((uint32_t)((brow+16)*128 + kb + bkad));
                asm volatile("ldmatrix.sync.aligned.m8n8.x4.shared.b16 {%0,%1,%2,%3}, [%4];"
                    : "=r"(bf[0]),"=r"(bf[1]),"=r"(bf[2]),"=r"(bf[3]) : "r"(ba0));
                asm volatile("ldmatrix.sync.aligned.m8n8.x4.shared.b16 {%0,%1,%2,%3}, [%4];"
                    : "=r"(bf[4]),"=r"(bf[5]),"=r"(bf[6]),"=r"(bf[7]) : "r"(ba1));
#pragma unroll
                for (int mi=0;mi<2;mi++){
                    uint32_t af[4];
                    uint32_t aa = aoff + SWZ((uint32_t)((arow+mi*16)*128 + kb + akad));
                    asm volatile("ldmatrix.sync.aligned.m8n8.x4.shared.b16 {%0,%1,%2,%3}, [%4];"
                        : "=r"(af[0]),"=r"(af[1]),"=r"(af[2]),"=r"(af[3]) : "r"(aa));
#pragma unroll
                    for (int ni=0;ni<4;ni++){
                        asm volatile(
                            "mma.sync.aligned.m16n8k16.row.col.f32.bf16.bf16.f32 "
                            "{%0,%1,%2,%3}, {%4,%5,%6,%7}, {%8,%9}, {%0,%1,%2,%3};"
                            : "+f"(acc[mi][ni][0]),"+f"(acc[mi][ni][1]),
                              "+f"(acc[mi][ni][2]),"+f"(acc[mi][ni][3])
                            : "r"(af[0]),"r"(af[1]),"r"(af[2]),"r"(af[3]),
                              "r"(bf[ni*2]),"r"(bf[ni*2+1]));
                    }
                }
            }
        }
        __syncthreads();
        if (i+4 < n) fill(i+4);
        CPA_COMMIT();
    }

    float* P = Ppart<L>() + (size_t)blk*4096;
#pragma unroll
    for (int mi=0;mi<2;mi++){
        int row = w*32 + mi*16 + (ln>>2);
#pragma unroll
        for (int ni=0;ni<4;ni++){
            int col = ni*8 + (ln&3)*2;
            *(float2*)(P + row*32 + col)     = make_float2(acc[mi][ni][0], acc[mi][ni][1]);
            *(float2*)(P + (row+8)*32 + col) = make_float2(acc[mi][ni][2], acc[mi][ni][3]);
        }
    }

    // ---- wait for all S partials of this jb (monotonic counter) ----
    __threadfence();
    __syncthreads();
    if (tid == 0){
        atomicAdd(&g_cnt[L][jb], 1);
        while (ld_acq(&g_cnt[L][jb]) < C::S * (t+1)) __nanosleep(32);
    }
    __syncthreads();

    // ---- distributed pointwise: this CTA handles its 32/S j-slice ----
    constexpr int JS = 32 / C::S;
    const int j0 = jb*32 + s*JS;
    const float* Pb = Ppart<L>() + (size_t)jb*C::S*4096;
    float* cst = g_c[L];
    __shared__ __nv_bfloat16 s_hi[8][34];
    __shared__ __nv_bfloat16 s_lo[8][34];
    __shared__ float s_f[8][33];

    constexpr int IT = (JS*32 + 127)/128;
#pragma unroll
    for (int it=0; it<IT; ++it){
        int item = tid + it*128;
        if (item < JS*32){
            int ljj = item>>5, b = item&31;
            int jj = s*JS + ljj;
            int j = jb*32 + jj;
            float hv = 0.f;
            if (j < C::OUT){
                float pre[4];
#pragma unroll
                for (int g=0; g<4; ++g){
                    float sum = 0.f;
                    for (int s2=0; s2<C::S; ++s2)
                        sum += Pb[(size_t)s2*4096 + (g*32+jj)*32 + b];
                    pre[g] = sum;
                }
                float ip, fp, op, gp;
                if (L == 0){
                    const float* p0 = g_P0 + ((size_t)t*M4H)*32 + b;
                    ip = pre[0] + p0[(size_t)(j       )*32] + bhh[j];
                    fp = pre[1] + p0[(size_t)(HH   + j)*32] + bhh[HH + j];
                    op = pre[2] + p0[(size_t)(2*HH + j)*32] + bhh[2*HH + j];
                    gp = pre[3] + p0[(size_t)(3*HH + j)*32] + bhh[3*HH + j];
                } else {
                    ip = pre[0] + bx[j]            + bhh[j];
                    fp = pre[1] + bx[C::OUT + j]   + bhh[C::OUT + j];
                    op = pre[2] + bx[2*C::OUT + j] + bhh[2*C::OUT + j];
                    gp = pre[3] + bx[3*C::OUT + j] + bhh[3*C::OUT + j];
                }
                float gi=1.f/(1.f+expf(-ip)), gf=1.f/(1.f+expf(-fp));
                float go=1.f/(1.f+expf(-op)), gg=tanhf(gp);
                float cn = gf*cst[j*32+b] + gi*gg;
                cst[j*32+b] = cn;
                hv = go*tanhf(cn);
                g_hf[L][j*32+b] = hv;
            }
            __nv_bfloat16 hbf = __float2bfloat16(hv);
            s_hi[ljj][b] = hbf;
            s_lo[ljj][b] = __float2bfloat16(hv - __bfloat162float(hbf));
            if (L == 2) s_f[ljj][b] = hv;
        }
    }
    __syncthreads();

    // ---- packed, coalesced staging stores ----
    if (L != 2){
        if (tid < 64){
            int tgt = tid >> 5, b = tid & 31;
            __nv_bfloat16* base;
            int kabs0;
            if (L == 0){ base = tgt ? gB1[par] : gB0[par^1]; kabs0 = j0; }
            else       { base = tgt ? gB2[par] : gB1[par^1]; kabs0 = tgt ? j0 : 1152 + j0; }
            int c = kabs0 >> 6, kk = kabs0 & 63;
            size_t pos = (size_t)c*4096 + (SWZ((uint32_t)(b*128 + kk*2)) >> 1);
            uint4 qh, ql;
            qh.x = pkbf(s_hi[0][b], s_hi[1][b]); qh.y = pkbf(s_hi[2][b], s_hi[3][b]);
            qh.z = pkbf(s_hi[4][b], s_hi[5][b]); qh.w = pkbf(s_hi[6][b], s_hi[7][b]);
            ql.x = pkbf(s_lo[0][b], s_lo[1][b]); ql.y = pkbf(s_lo[2][b], s_lo[3][b]);
            ql.z = pkbf(s_lo[4][b], s_lo[5][b]); ql.w = pkbf(s_lo[6][b], s_lo[7][b]);
            *(uint4*)(base + pos)        = qh;
            *(uint4*)(base + 2048 + pos) = ql;
        }
    } else {
        if (tid < 32){
            int b = tid;
            __nv_bfloat16* base = gB2[par^1];
            int kabs0 = 1152 + j0;
            int c = kabs0 >> 6, kk = kabs0 & 63;
            size_t pos = (size_t)c*4096 + (SWZ((uint32_t)(b*128 + kk*2)) >> 1);
            uint2 qh, ql;
            qh.x = pkbf(s_hi[0][b], s_hi[1][b]); qh.y = pkbf(s_hi[2][b], s_hi[3][b]);
            ql.x = pkbf(s_lo[0][b], s_lo[1][b]); ql.y = pkbf(s_lo[2][b], s_lo[3][b]);
            *(uint2*)(base + pos)        = qh;
            *(uint2*)(base + 2048 + pos) = ql;
        } else if (tid < 64){
            int b = tid - 32;
            if (j0 + JS <= C::OUT){
                float4 f = make_float4(s_f[0][b], s_f[1][b], s_f[2][b], s_f[3][b]);
                *(float4*)(g_h2all + ((size_t)(t*32 + b))*EE + j0) = f;
            }
        }
    }
}

__global__ __launch_bounds__(128) void recurrence(
    const float* __restrict__ bh0,
    const float* __restrict__ bi1, const float* __restrict__ bh1,
    const float* __restrict__ bi2, const float* __restrict__ bh2)
{
    extern __shared__ __align__(128) char sm[];
    // kernel-start resets (replay-safe; ordered before use by gridbar(0))
    if (blockIdx.x == 0){
        if (threadIdx.x == 0) atomicExch(&g_barslot[2*TT], 0);
        if (threadIdx.x < 36)       g_cnt[0][threadIdx.x]      = 0;
        else if (threadIdx.x < 72)  g_cnt[1][threadIdx.x - 36] = 0;
        else if (threadIdx.x < 85)  g_cnt[2][threadIdx.x - 72] = 0;
    }
    gridbar(0);
    int slot = 1;
    for (int t = 0; t < TT; ++t){
        do_layer<0>(sm, nullptr, bh0, t);
        gridbar(slot++);
        do_layer<1>(sm, bi1, bh1, t);
        gridbar(slot++);
        do_layer<2>(sm, bi2, bh2, t);
        // no barrier: L2(t) conflicts with nothing before post-L0(t+1) barrier
    }
}

// ---- init / finalize ----
__global__ void init_states(const float* __restrict__ h0,
                            const float* __restrict__ c0,
                            const float* __restrict__ h0l,
                            const float* __restrict__ c0l)
{
    int idx = blockIdx.x*blockDim.x + threadIdx.x;
    if (idx < HH*BB){
        int k = idx>>5, b = idx&31;
        g_c[0][idx] = c0[b*HH + k];
        g_c[1][idx] = c0[BB*HH + b*HH + k];
        stageB(gB0[0], k,        b, h0[b*HH + k]);
        stageB(gB1[0], 1152 + k, b, h0[BB*HH + b*HH + k]);
    }
    if (idx < EE*BB){
        int k = idx>>5, b = idx&31;
        g_c[2][idx] = c0l[b*EE + k];
        stageB(gB2[0], 1152 + k, b, h0l[b*EE + k]);
    }
}

__global__ void finalize_states(float* __restrict__ out)
{
    const size_t D1 = (size_t)TT*BB*VV;
    const size_t D2 = D1 + 2*BB*HH;
    const size_t D3 = D2 + BB*EE;
    const size_t D4 = D3 + 2*BB*HH;
    int idx = blockIdx.x*blockDim.x + threadIdx.x;
    if (idx < HH*BB){
        int k = idx>>5, b = idx&31;
        out[D1 + b*HH + k]           = g_hf[0][idx];
        out[D1 + BB*HH + b*HH + k]   = g_hf[1][idx];
        out[D3 + b*HH + k]           = g_c[0][idx];
        out[D3 + BB*HH + b*HH + k]   = g_c[1][idx];
    }
    if (idx < EE*BB){
        int k = idx>>5, b = idx&31;
        out[D2 + b*EE + k] = g_hf[2][idx];
        out[D4 + b*EE + k] = g_c[2][idx];
    }
}

// =======================================================================
extern "C" void kernel_launch(void* const* d_in, const int* in_sizes, int n_in,
                              void* d_out, int out_size)
{
    const int*   x    = (const int*)  d_in[0];
    const float* h0   = (const float*)d_in[1];
    const float* c0   = (const float*)d_in[2];
    const float* h0l  = (const float*)d_in[3];
    const float* c0l  = (const float*)d_in[4];
    const float* emb  = (const float*)d_in[5];
    const float* Wi0  = (const float*)d_in[6];
    const float* bi0  = (const float*)d_in[7];
    const float* Wh0  = (const float*)d_in[8];
    const float* bh0  = (const float*)d_in[9];
    const float* Wi1  = (const float*)d_in[10];
    const float* bi1  = (const float*)d_in[11];
    const float* Wh1  = (const float*)d_in[12];
    const float* bh1  = (const float*)d_in[13];
    const float* Wi2  = (const float*)d_in[14];
    const float* bi2  = (const float*)d_in[15];
    const float* Wh2  = (const float*)d_in[16];
    const float* bh2  = (const float*)d_in[17];
    const float* decW = (const float*)d_in[18];
    const float* decb = (const float*)d_in[19];
    float* out = (float*)d_out;

    cudaFuncSetAttribute(recurrence, cudaFuncAttributeMaxDynamicSharedMemorySize, SMEM_MMA);

    init_states<<<(HH*BB + 255)/256, 256>>>(h0, c0, h0l, c0l);

    prep_A<0><<<(36*18*8192 + 255)/256, 256>>>(nullptr, Wh0);
    prep_A<1><<<(36*36*8192 + 255)/256, 256>>>(Wi1, Wh1);
    prep_A<2><<<(13*25*8192 + 255)/256, 256>>>(Wi2, Wh2);

    {   // P0 = emb[x] @ Wi0^T + bi0 (written transposed [t][col][b])
        dim3 g((M4H + 63)/64, NROW/64);
        sgemm_nt<0><<<g, 256>>>(emb, x, Wi0, bi0, nullptr, M4H);
    }

    recurrence<<<NCTA, 128, SMEM_MMA>>>(bh0, bi1, bh1, bi2, bh2);

    {   // decoder
        dim3 g((VV + 63)/64, NROW/64);
        sgemm_nt<1><<<g, 256>>>(nullptr, nullptr, decW, decb, out, VV);
    }

    finalize_states<<<(HH*BB + 255)/256, 256>>>(out);
}

// round 15
// speedup vs baseline: 1.8330x; 1.0730x over previous
#include <cuda_runtime.h>
#include <cuda_bf16.h>
#include <math.h>
#include <stdint.h>

#define EE   400
#define HH   1150
#define VV   10000
#define TT   256
#define BB   32
#define M4H  4600
#define NROW 8192
#define NT0  36
#define NT1  72
#define NT2  26
#define NTOT 134
typedef unsigned long long ull;

template<int L> struct LC;
template<> struct LC<0>{ enum{OUT=1150,NJB=36,NCH=18,S=1,KH=1150}; };
template<> struct LC<1>{ enum{OUT=1150,NJB=36,NCH=36,S=2,KH=1150}; };
template<> struct LC<2>{ enum{OUT=400, NJB=13,NCH=25,S=2,KH=400 }; };

// ---------------- device scratch ----------------
__device__ __align__(16) float g_P0[(size_t)NROW * M4H];   // TRANSPOSED [t][4600][b]
__device__ __align__(16) float g_h2all[(size_t)NROW * EE];
__device__ __align__(16) float g_c[3][HH * BB];
__device__ __align__(16) float g_hf[3][HH * BB];
__device__ __align__(16) __nv_bfloat16 gA0[(size_t)36*18*16384];
__device__ __align__(16) __nv_bfloat16 gA1[(size_t)36*36*16384];
__device__ __align__(16) __nv_bfloat16 gA2[(size_t)13*25*16384];
__device__ __align__(16) __nv_bfloat16 gB0[2][18*4096];
__device__ __align__(16) __nv_bfloat16 gB1[2][36*4096];
__device__ __align__(16) __nv_bfloat16 gB2[2][25*4096];
__device__ __align__(16) float gPart1[2][72*4096];   // parity double-buffered
__device__ __align__(16) float gPart2[2][26*4096];
__device__ int g_cA, g_cB, g_cC;   // monotonic per launch; reset at shutdown
__device__ int g_jbc[49];          // 36 L1 + 13 L2, monotonic
__device__ int g_end[3];           // shutdown handshake

template<int L> __device__ __forceinline__ __nv_bfloat16* Apack(){
    return (L==0) ? gA0 : (L==1) ? gA1 : gA2;
}
template<int L> __device__ __forceinline__ __nv_bfloat16* Bpack(int par){
    return (L==0) ? gB0[par] : (L==1) ? gB1[par] : gB2[par];
}

// ---------------- helpers ----------------
#define SWZ(x) ((x) ^ (((x) >> 3) & 0x70))
__device__ __forceinline__ uint32_t smem_u32(const void* p){
    uint32_t a;
    asm("{ .reg .u64 t; cvta.to.shared.u64 t, %1; cvt.u32.u64 %0, t; }" : "=r"(a) : "l"(p));
    return a;
}
__device__ __forceinline__ void cpa16(uint32_t dst, const void* src){
    asm volatile("cp.async.cg.shared.global [%0], [%1], 16;" :: "r"(dst), "l"(src));
}
#define CPA_COMMIT() asm volatile("cp.async.commit_group;" ::: "memory")
__device__ __forceinline__ int ld_acq(const int* p){
    int v; asm volatile("ld.acquire.gpu.b32 %0, [%1];" : "=r"(v) : "l"(p) : "memory");
    return v;
}
__device__ __forceinline__ float ldcg(const float* p){
    float v; asm volatile("ld.global.cg.f32 %0, [%1];" : "=f"(v) : "l"(p)); return v;
}
__device__ __forceinline__ void waitge(int* ctr, int target){
    if (threadIdx.x == 0){
        while (ld_acq(ctr) < target) __nanosleep(64);
    }
    __syncthreads();
}

// element-wise staging (init only)
__device__ __forceinline__ void stageB(__nv_bfloat16* base, int kabs, int b, float v){
    int c = kabs >> 6, kk = kabs & 63;
    uint32_t pos = SWZ((uint32_t)(b*128 + kk*2)) >> 1;
    __nv_bfloat16 h = __float2bfloat16(v);
    base[(size_t)c*4096 + pos]        = h;
    base[(size_t)c*4096 + 2048 + pos] = __float2bfloat16(v - __bfloat162float(h));
}

__device__ __forceinline__ void fma2(ull& d, ull a, ull b){
    asm("fma.rn.f32x2 %0, %1, %2, %0;" : "+l"(d) : "l"(a), "l"(b));
}
__device__ __forceinline__ ull dup2(float x){
    ull r; asm("mov.b64 %0, {%1, %2};" : "=l"(r) : "f"(x), "f"(x)); return r;
}
__device__ __forceinline__ float2 unp2(ull v){
    float2 r; asm("mov.b64 {%0, %1}, %2;" : "=f"(r.x), "=f"(r.y) : "l"(v)); return r;
}
__device__ __forceinline__ uint32_t pkbf(__nv_bfloat16 a, __nv_bfloat16 b){
    return (uint32_t)__bfloat16_as_ushort(a) | ((uint32_t)__bfloat16_as_ushort(b) << 16);
}

// =======================================================================
// fp32 SGEMM. MODE 0: gather + bias -> transposed g_P0. MODE 1: decoder.
// =======================================================================
template<int MODE>
__global__ __launch_bounds__(256) void sgemm_nt(
    const float* __restrict__ A, const int* __restrict__ gidx,
    const float* __restrict__ Bm, const float* __restrict__ bias,
    float* __restrict__ Cout, int N)
{
    const int K = EE;
    __shared__ __align__(16) float As[16][68];
    __shared__ __align__(16) float Bs[16][68];
    const float* Abase = (MODE==1) ? g_h2all : A;
    const int tid = threadIdx.x;
    const int bm = blockIdx.y*64, bn = blockIdx.x*64;
    const int r = tid>>2, q = tid&3;
    const float* arow = (MODE==0) ? Abase + (size_t)gidx[bm+r]*K : Abase + (size_t)(bm+r)*K;
    const int nrow = bn + r;
    const bool bok = nrow < N;
    const float* brow = Bm + (size_t)(bok ? nrow : (N-1))*K;
    const int tx = tid&15, ty = tid>>4;
    ull acc[4][2];
#pragma unroll
    for (int i=0;i<4;++i){ acc[i][0]=0ull; acc[i][1]=0ull; }
    for (int kc=0;kc<K;kc+=16){
        float4 av = *(const float4*)(arow + kc + q*4);
        float4 bv = *(const float4*)(brow + kc + q*4);
        if (!bok){ bv.x=bv.y=bv.z=bv.w=0.f; }
        __syncthreads();
        As[q*4+0][r]=av.x; As[q*4+1][r]=av.y; As[q*4+2][r]=av.z; As[q*4+3][r]=av.w;
        Bs[q*4+0][r]=bv.x; Bs[q*4+1][r]=bv.y; Bs[q*4+2][r]=bv.z; Bs[q*4+3][r]=bv.w;
        __syncthreads();
#pragma unroll
        for (int k=0;k<16;++k){
            ull b0 = *(const ull*)&Bs[k][tx*4];
            ull b1 = *(const ull*)&Bs[k][tx*4+2];
            float4 a4 = *(const float4*)&As[k][ty*4];
            ull a;
            a=dup2(a4.x); fma2(acc[0][0],a,b0); fma2(acc[0][1],a,b1);
            a=dup2(a4.y); fma2(acc[1][0],a,b0); fma2(acc[1][1],a,b1);
            a=dup2(a4.z); fma2(acc[2][0],a,b0); fma2(acc[2][1],a,b1);
            a=dup2(a4.w); fma2(acc[3][0],a,b0); fma2(acc[3][1],a,b1);
        }
    }
    if constexpr (MODE == 0){
        __shared__ float Ts[64][65];
        __syncthreads();
#pragma unroll
        for (int i=0;i<4;++i){
            float2 c0=unp2(acc[i][0]), c1=unp2(acc[i][1]);
            float v[4]={c0.x,c0.y,c1.x,c1.y};
#pragma unroll
            for (int j=0;j<4;++j){
                int col = bn + tx*4 + j;
                Ts[ty*4+i][tx*4+j] = v[j] + (col < N ? bias[col] : 0.f);
            }
        }
        __syncthreads();
        for (int idx=tid; idx<4096; idx+=256){
            int cl = idx>>6, rl = idx&63;
            int col = bn + cl;
            if (col < N){
                int row = bm + rl;
                int t = row>>5, b = row&31;
                g_P0[((size_t)t*M4H + col)*32 + b] = Ts[rl][cl];
            }
        }
    } else {
#pragma unroll
        for (int i=0;i<4;++i){
            int row = bm + ty*4 + i;
            float2 c0=unp2(acc[i][0]), c1=unp2(acc[i][1]);
            float v[4]={c0.x,c0.y,c1.x,c1.y};
#pragma unroll
            for (int j=0;j<4;++j){
                int col = bn + tx*4 + j;
                if (col < N) Cout[(size_t)row*N + col] = v[j] + bias[col];
            }
        }
    }
}

// =======================================================================
// A-pack prep (KXP padding 1152 for L1/L2)
// =======================================================================
template<int L>
__global__ void prep_A(const float* __restrict__ Wi, const float* __restrict__ Wh)
{
    using C = LC<L>;
    const int KXP = (L==0) ? 0 : 1152;
    size_t idx = (size_t)blockIdx.x*256 + threadIdx.x;
    size_t total = (size_t)C::NJB*C::NCH*8192;
    if (idx >= total) return;
    int kk  = (int)(idx & 63);
    int row = (int)((idx>>6) & 127);
    int ch  = (int)((idx>>13) % C::NCH);
    int jb  = (int)(idx / ((size_t)C::NCH*8192));
    int gate = row>>5, j = jb*32 + (row&31);
    int kabs = ch*64 + kk;
    float v = 0.f;
    if (j < C::OUT){
        if (L != 0 && kabs < 1150)
            v = Wi[(size_t)(gate*C::OUT + j)*1150 + kabs];
        else if (kabs >= KXP && kabs - KXP < C::KH)
            v = Wh[(size_t)(gate*C::OUT + j)*C::KH + (kabs - KXP)];
    }
    __nv_bfloat16 h = __float2bfloat16(v);
    __nv_bfloat16 l = __float2bfloat16(v - __bfloat162float(h));
    uint32_t pos = SWZ((uint32_t)(row*128 + kk*2)) >> 1;
    __nv_bfloat16* Ap = Apack<L>() + (size_t)(jb*C::NCH + ch)*16384;
    Ap[pos] = h;
    Ap[8192 + pos] = l;
}

// =======================================================================
// MMA over a chunk list (4-deep cp.async pipeline, 3 bf16-split passes)
// =======================================================================
#define STGB 40960
#define SMEM_MMA (4*STGB)

__device__ __forceinline__ void mma_chunks(
    uint32_t sb, const __nv_bfloat16* Ab, const __nv_bfloat16* Bb,
    const int* cl, int cnt, float (&acc)[2][4][4])
{
    if (cnt <= 0) return;
    const int tid = threadIdx.x;
    const int w = tid>>5, ln = tid&31;
    const int arow = w*32 + (ln&7) + ((ln>>3)&1)*8;
    const int akad = ((ln>>4)&1)*16;
    const int brow = ((ln>>4)&1)*8 + (ln&7);
    const int bkad = ((ln>>3)&1)*16;

    auto fill = [&](int i){
        uint32_t dst = sb + (i & 3)*STGB;
        int c = cl[i];
        const char* a = (const char*)(Ab + (size_t)c*16384);
#pragma unroll
        for (int r=0;r<16;r++) cpa16(dst + r*2048 + tid*16, a + r*2048 + tid*16);
        const char* b = (const char*)(Bb + (size_t)c*4096);
#pragma unroll
        for (int r=0;r<4;r++) cpa16(dst + 32768 + r*2048 + tid*16, b + r*2048 + tid*16);
    };
    for (int i=0;i<4;i++){ if (i<cnt) fill(i); CPA_COMMIT(); }

    for (int i=0;i<cnt;i++){
        asm volatile("cp.async.wait_group 3;" ::: "memory");
        __syncthreads();
        uint32_t so = sb + (i & 3)*STGB;
#pragma unroll
        for (int p=0;p<3;p++){
            uint32_t aoff = so + ((p==2)?16384u:0u);
            uint32_t boff = so + ((p==1)?36864u:32768u);
#pragma unroll
            for (int ks=0;ks<4;ks++){
                const int kb = ks*32;
                uint32_t bf[8];
                uint32_t ba0 = boff + SWZ((uint32_t)(brow*128 + kb + bkad));
                uint32_t ba1 = boff + SWZ((uint32_t)((brow+16)*128 + kb + bkad));
                asm volatile("ldmatrix.sync.aligned.m8n8.x4.shared.b16 {%0,%1,%2,%3}, [%4];"
                    : "=r"(bf[0]),"=r"(bf[1]),"=r"(bf[2]),"=r"(bf[3]) : "r"(ba0));
                asm volatile("ldmatrix.sync.aligned.m8n8.x4.shared.b16 {%0,%1,%2,%3}, [%4];"
                    : "=r"(bf[4]),"=r"(bf[5]),"=r"(bf[6]),"=r"(bf[7]) : "r"(ba1));
#pragma unroll
                for (int mi=0;mi<2;mi++){
                    uint32_t af[4];
                    uint32_t aa = aoff + SWZ((uint32_t)((arow+mi*16)*128 + kb + akad));
                    asm volatile("ldmatrix.sync.aligned.m8n8.x4.shared.b16 {%0,%1,%2,%3}, [%4];"
                        : "=r"(af[0]),"=r"(af[1]),"=r"(af[2]),"=r"(af[3]) : "r"(aa));
#pragma unroll
                    for (int ni=0;ni<4;ni++){
                        asm volatile(
                            "mma.sync.aligned.m16n8k16.row.col.f32.bf16.bf16.f32 "
                            "{%0,%1,%2,%3}, {%4,%5,%6,%7}, {%8,%9}, {%0,%1,%2,%3};"
                            : "+f"(acc[mi][ni][0]),"+f"(acc[mi][ni][1]),
                              "+f"(acc[mi][ni][2]),"+f"(acc[mi][ni][3])
                            : "r"(af[0]),"r"(af[1]),"r"(af[2]),"r"(af[3]),
                              "r"(bf[ni*2]),"r"(bf[ni*2+1]));
                    }
                }
            }
        }
        __syncthreads();
        if (i+4 < cnt) fill(i+4);
        CPA_COMMIT();
    }
}

// =======================================================================
// One layer-step for a dedicated CTA (spatial pipeline stage)
// =======================================================================
template<int L>
__device__ __forceinline__ void step_layer(
    char* sm, const float* __restrict__ bx, const float* __restrict__ bhh,
    int t, int jb, int s)
{
    using C = LC<L>;
    const int tid = threadIdx.x;
    const int par = t & 1;
    uint32_t sb = smem_u32(sm);
    const __nv_bfloat16* Ab = Apack<L>() + (size_t)jb*C::NCH*16384;
    const __nv_bfloat16* Bb = Bpack<L>(par);

    float acc[2][4][4];
#pragma unroll
    for (int mi=0;mi<2;mi++)
#pragma unroll
        for (int ni=0;ni<4;ni++)
#pragma unroll
            for (int q=0;q<4;q++) acc[mi][ni][q]=0.f;

    // chunk lists: l1 = "ready" (h) chunks, l2 = x chunks needing upstream
    int l1[18], l2[9]; int n1=0, n2=0;
    if (L == 0){
        for (int c=0;c<18;c++) l1[n1++]=c;
    } else if (L == 1){
        for (int c=18;c<36;c++) if ((c&1)==s) l1[n1++]=c;
        for (int c=0;c<18;c++)  if ((c&1)==s) l2[n2++]=c;
    } else {
        for (int c=18;c<25;c++) if ((c&1)==s) l1[n1++]=c;
        for (int c=0;c<18;c++)  if ((c&1)==s) l2[n2++]=c;
    }

    // h readiness (own group's previous step)
    if (L == 0)      waitge(&g_cA, NT0*t);
    else if (L == 1) waitge(&g_cB, NT1*t);
    else             waitge(&g_cC, NT2*t);
    mma_chunks(sb, Ab, Bb, l1, n1, acc);
    if (L == 1){ waitge(&g_cA, NT0*(t+1)); mma_chunks(sb, Ab, Bb, l2, n2, acc); }
    if (L == 2){ waitge(&g_cB, NT1*(t+1)); mma_chunks(sb, Ab, Bb, l2, n2, acc); }

    // ---- partials ----
    const int w = tid>>5, ln = tid&31;
    __syncthreads();
    if (L == 0){
        float* sacc = (float*)sm;     // aliases stage buffers (idle now)
#pragma unroll
        for (int mi=0;mi<2;mi++){
            int row = w*32 + mi*16 + (ln>>2);
#pragma unroll
            for (int ni=0;ni<4;ni++){
                int col = ni*8 + (ln&3)*2;
                *(float2*)(sacc + row*32 + col)     = make_float2(acc[mi][ni][0], acc[mi][ni][1]);
                *(float2*)(sacc + (row+8)*32 + col) = make_float2(acc[mi][ni][2], acc[mi][ni][3]);
            }
        }
        __syncthreads();
    } else {
        float* P = ((L==1) ? gPart1[par] : gPart2[par]) + (size_t)(jb*2+s)*4096;
#pragma unroll
        for (int mi=0;mi<2;mi++){
            int row = w*32 + mi*16 + (ln>>2);
#pragma unroll
            for (int ni=0;ni<4;ni++){
                int col = ni*8 + (ln&3)*2;
                *(float2*)(P + row*32 + col)     = make_float2(acc[mi][ni][0], acc[mi][ni][1]);
                *(float2*)(P + (row+8)*32 + col) = make_float2(acc[mi][ni][2], acc[mi][ni][3]);
            }
        }
        __threadfence();
        __syncthreads();
        int* jc = &g_jbc[((L==1) ? 0 : 36) + jb];
        if (tid == 0){
            atomicAdd(jc, 1);
            while (ld_acq(jc) < 2*(t+1)) __nanosleep(64);
        }
        __syncthreads();
    }

    // ---- pointwise on this CTA's j-slice ----
    constexpr int JS = (L==0) ? 32 : 16;
    const int j0 = jb*32 + s*JS;
    __nv_bfloat16* shi = (__nv_bfloat16*)(sm + 16384);
    __nv_bfloat16* slo = (__nv_bfloat16*)(sm + 20608);
    float*         sf  = (float*)(sm + 24832);
    float* cst = g_c[L];
    constexpr int IT = JS*32/128;
#pragma unroll
    for (int it=0; it<IT; ++it){
        int item = tid + it*128;
        int ljj = item>>5, b = item&31;
        int j = j0 + ljj;
        int jj = s*JS + ljj;
        float hv = 0.f;
        if (j < C::OUT){
            float pre[4];
            if (L == 0){
                const float* sacc = (const float*)sm;
#pragma unroll
                for (int g=0; g<4; ++g) pre[g] = sacc[(g*32+jj)*32 + b];
            } else {
                const float* Pb = ((L==1) ? gPart1[par] : gPart2[par]) + (size_t)jb*2*4096;
#pragma unroll
                for (int g=0; g<4; ++g)
                    pre[g] = ldcg(Pb + (g*32+jj)*32 + b) + ldcg(Pb + 4096 + (g*32+jj)*32 + b);
            }
            float ip, fp, op, gp;
            if (L == 0){
                const float* p0 = g_P0 + ((size_t)t*M4H)*32 + b;
                ip = pre[0] + p0[(size_t)(j       )*32] + bhh[j];
                fp = pre[1] + p0[(size_t)(HH   + j)*32] + bhh[HH + j];
                op = pre[2] + p0[(size_t)(2*HH + j)*32] + bhh[2*HH + j];
                gp = pre[3] + p0[(size_t)(3*HH + j)*32] + bhh[3*HH + j];
            } else {
                ip = pre[0] + bx[j]            + bhh[j];
                fp = pre[1] + bx[C::OUT + j]   + bhh[C::OUT + j];
                op = pre[2] + bx[2*C::OUT + j] + bhh[2*C::OUT + j];
                gp = pre[3] + bx[3*C::OUT + j] + bhh[3*C::OUT + j];
            }
            float gi=1.f/(1.f+expf(-ip)), gf=1.f/(1.f+expf(-fp));
            float go=1.f/(1.f+expf(-op)), gg=tanhf(gp);
            float cn = gf*cst[j*32+b] + gi*gg;
            cst[j*32+b] = cn;
            hv = go*tanhf(cn);
            g_hf[L][j*32+b] = hv;
        }
        __nv_bfloat16 hbf = __float2bfloat16(hv);
        shi[ljj*33+b] = hbf;
        slo[ljj*33+b] = __float2bfloat16(hv - __bfloat162float(hbf));
        if (L == 2) sf[ljj*33+b] = hv;
    }
    __syncthreads();

    // ---- packed staging stores ----
    constexpr int NBLK = JS/8;
    if (L != 2){
        const int total = 2*32*NBLK;
        for (int idx=tid; idx<total; idx+=128){
            int tgt = idx / (32*NBLK);
            int rem = idx % (32*NBLK);
            int b = rem & 31, bq = rem >> 5;
            __nv_bfloat16* base; int kabs0;
            if (L == 0){ base = tgt ? gB1[par] : gB0[par^1]; kabs0 = j0; }
            else       { base = tgt ? gB2[par] : gB1[par^1]; kabs0 = tgt ? j0 : 1152 + j0; }
            int kabs = kabs0 + bq*8;
            int c = kabs >> 6, kk = kabs & 63;
            size_t pos = (size_t)c*4096 + (SWZ((uint32_t)(b*128 + kk*2)) >> 1);
            int r0 = bq*8;
            uint4 qh = make_uint4(
                pkbf(shi[(r0+0)*33+b], shi[(r0+1)*33+b]),
                pkbf(shi[(r0+2)*33+b], shi[(r0+3)*33+b]),
                pkbf(shi[(r0+4)*33+b], shi[(r0+5)*33+b]),
                pkbf(shi[(r0+6)*33+b], shi[(r0+7)*33+b]));
            uint4 ql = make_uint4(
                pkbf(slo[(r0+0)*33+b], slo[(r0+1)*33+b]),
                pkbf(slo[(r0+2)*33+b], slo[(r0+3)*33+b]),
                pkbf(slo[(r0+4)*33+b], slo[(r0+5)*33+b]),
                pkbf(slo[(r0+6)*33+b], slo[(r0+7)*33+b]));
            *(uint4*)(base + pos)        = qh;
            *(uint4*)(base + pos + 2048) = ql;
        }
    } else {
        if (tid < 64 && j0 < C::OUT){
            int b = tid & 31, bq = tid >> 5;
            int kabs = 1152 + j0 + bq*8;
            int c = kabs >> 6, kk = kabs & 63;
            size_t pos = (size_t)c*4096 + (SWZ((uint32_t)(b*128 + kk*2)) >> 1);
            int r0 = bq*8;
            uint4 qh = make_uint4(
                pkbf(shi[(r0+0)*33+b], shi[(r0+1)*33+b]),
                pkbf(shi[(r0+2)*33+b], shi[(r0+3)*33+b]),
                pkbf(shi[(r0+4)*33+b], shi[(r0+5)*33+b]),
                pkbf(shi[(r0+6)*33+b], shi[(r0+7)*33+b]));
            uint4 ql = make_uint4(
                pkbf(slo[(r0+0)*33+b], slo[(r0+1)*33+b]),
                pkbf(slo[(r0+2)*33+b], slo[(r0+3)*33+b]),
                pkbf(slo[(r0+4)*33+b], slo[(r0+5)*33+b]),
                pkbf(slo[(r0+6)*33+b], slo[(r0+7)*33+b]));
            __nv_bfloat16* base = gB2[par^1];
            *(uint4*)(base + pos)        = qh;
            *(uint4*)(base + pos + 2048) = ql;
        }
        {   // g_h2all float4 writes
            int b = tid & 31, bq = tid >> 5;   // 4 blocks of 4 floats
            if (j0 < C::OUT){
                float4 f = make_float4(sf[(bq*4+0)*33+b], sf[(bq*4+1)*33+b],
                                       sf[(bq*4+2)*33+b], sf[(bq*4+3)*33+b]);
                *(float4*)(g_h2all + (size_t)(t*32 + b)*EE + j0 + bq*4) = f;
            }
        }
    }

    __threadfence();
    __syncthreads();
    if (tid == 0){
        if (L == 0)      atomicAdd(&g_cA, 1);
        else if (L == 1) atomicAdd(&g_cB, 1);
        else             atomicAdd(&g_cC, 1);
    }
}

// =======================================================================
// Persistent spatially-pipelined recurrence: 36 L0 + 72 L1 + 26 L2 CTAs
// =======================================================================
__global__ __launch_bounds__(128) void recurrence(
    const float* __restrict__ bh0,
    const float* __restrict__ bi1, const float* __restrict__ bh1,
    const float* __restrict__ bi2, const float* __restrict__ bh2)
{
    extern __shared__ __align__(128) char sm[];
    const int blk = blockIdx.x;

    if (blk < NT0){
        for (int t=0; t<TT; ++t) step_layer<0>(sm, nullptr, bh0, t, blk, 0);
    } else if (blk < NT0 + NT1){
        int r = blk - NT0;
        for (int t=0; t<TT; ++t) step_layer<1>(sm, bi1, bh1, t, r>>1, r&1);
    } else {
        int r = blk - NT0 - NT1;
        for (int t=0; t<TT; ++t) step_layer<2>(sm, bi2, bh2, t, r>>1, r&1);
    }

    // ---- replay-safe shutdown: reset all counters ----
    __syncthreads();
    if (threadIdx.x == 0){
        atomicAdd(&g_end[0], 1);
        if (blk == 0){
            while (ld_acq(&g_end[0]) < NTOT) __nanosleep(128);
            g_cA = 0; g_cB = 0; g_cC = 0;
            for (int i=0;i<49;i++) g_jbc[i] = 0;
            g_end[0] = 0;
            __threadfence();
            atomicExch(&g_end[1], 1);
            while (ld_acq(&g_end[2]) < NTOT-1) __nanosleep(128);
            g_end[2] = 0;
            __threadfence();
            atomicExch(&g_end[1], 0);
        } else {
            while (ld_acq(&g_end[1]) == 0) __nanosleep(128);
            atomicAdd(&g_end[2], 1);
        }
    }
}

// ---- init / finalize ----
__global__ void init_states(const float* __restrict__ h0,
                            const float* __restrict__ c0,
                            const float* __restrict__ h0l,
                            const float* __restrict__ c0l)
{
    int idx = blockIdx.x*blockDim.x + threadIdx.x;
    if (idx < HH*BB){
        int k = idx>>5, b = idx&31;
        g_c[0][idx] = c0[b*HH + k];
        g_c[1][idx] = c0[BB*HH + b*HH + k];
        stageB(gB0[0], k,        b, h0[b*HH + k]);
        stageB(gB1[0], 1152 + k, b, h0[BB*HH + b*HH + k]);
    }
    if (idx < EE*BB){
        int k = idx>>5, b = idx&31;
        g_c[2][idx] = c0l[b*EE + k];
        stageB(gB2[0], 1152 + k, b, h0l[b*EE + k]);
    }
}

__global__ void finalize_states(float* __restrict__ out)
{
    const size_t D1 = (size_t)TT*BB*VV;
    const size_t D2 = D1 + 2*BB*HH;
    const size_t D3 = D2 + BB*EE;
    const size_t D4 = D3 + 2*BB*HH;
    int idx = blockIdx.x*blockDim.x + threadIdx.x;
    if (idx < HH*BB){
        int k = idx>>5, b = idx&31;
        out[D1 + b*HH + k]           = g_hf[0][idx];
        out[D1 + BB*HH + b*HH + k]   = g_hf[1][idx];
        out[D3 + b*HH + k]           = g_c[0][idx];
        out[D3 + BB*HH + b*HH + k]   = g_c[1][idx];
    }
    if (idx < EE*BB){
        int k = idx>>5, b = idx&31;
        out[D2 + b*EE + k] = g_hf[2][idx];
        out[D4 + b*EE + k] = g_c[2][idx];
    }
}

// =======================================================================
extern "C" void kernel_launch(void* const* d_in, const int* in_sizes, int n_in,
                              void* d_out, int out_size)
{
    const int*   x    = (const int*)  d_in[0];
    const float* h0   = (const float*)d_in[1];
    const float* c0   = (const float*)d_in[2];
    const float* h0l  = (const float*)d_in[3];
    const float* c0l  = (const float*)d_in[4];
    const float* emb  = (const float*)d_in[5];
    const float* Wi0  = (const float*)d_in[6];
    const float* bi0  = (const float*)d_in[7];
    const float* Wh0  = (const float*)d_in[8];
    const float* bh0  = (const float*)d_in[9];
    const float* Wi1  = (const float*)d_in[10];
    const float* bi1  = (const float*)d_in[11];
    const float* Wh1  = (const float*)d_in[12];
    const float* bh1  = (const float*)d_in[13];
    const float* Wi2  = (const float*)d_in[14];
    const float* bi2  = (const float*)d_in[15];
    const float* Wh2  = (const float*)d_in[16];
    const float* bh2  = (const float*)d_in[17];
    const float* decW = (const float*)d_in[18];
    const float* decb = (const float*)d_in[19];
    float* out = (float*)d_out;

    cudaFuncSetAttribute(recurrence, cudaFuncAttributeMaxDynamicSharedMemorySize, SMEM_MMA);

    init_states<<<(HH*BB + 255)/256, 256>>>(h0, c0, h0l, c0l);

    prep_A<0><<<(36*18*8192 + 255)/256, 256>>>(nullptr, Wh0);
    prep_A<1><<<(36*36*8192 + 255)/256, 256>>>(Wi1, Wh1);
    prep_A<2><<<(13*25*8192 + 255)/256, 256>>>(Wi2, Wh2);

    {   // P0 = emb[x] @ Wi0^T + bi0 (written transposed [t][col][b])
        dim3 g((M4H + 63)/64, NROW/64);
        sgemm_nt<0><<<g, 256>>>(emb, x, Wi0, bi0, nullptr, M4H);
    }

    recurrence<<<NTOT, 128, SMEM_MMA>>>(bh0, bi1, bh1, bi2, bh2);

    {   // decoder
        dim3 g((VV + 63)/64, NROW/64);
        sgemm_nt<1><<<g, 256>>>(nullptr, nullptr, decW, decb, out, VV);
    }

    finalize_states<<<(HH*BB + 255)/256, 256>>>(out);
}

// round 16
// speedup vs baseline: 2.0976x; 1.1444x over previous
#include <cuda_runtime.h>
#include <cuda_bf16.h>
#include <cuda_fp16.h>
#include <math.h>
#include <stdint.h>

#define EE   400
#define HH   1150
#define VV   10000
#define TT   256
#define BB   32
#define M4H  4600
#define NROW 8192
#define NT0  36
#define NT1  72
#define NT2  26
#define NTOT 134
typedef unsigned long long ull;

template<int L> struct LC;
template<> struct LC<0>{ enum{OUT=1150,NJB=36,NCH=18,S=1,KH=1150}; };
template<> struct LC<1>{ enum{OUT=1150,NJB=36,NCH=36,S=2,KH=1150}; };
template<> struct LC<2>{ enum{OUT=400, NJB=13,NCH=25,S=2,KH=400 }; };

// ---------------- device scratch ----------------
__device__ __align__(16) float g_P0[(size_t)NROW * M4H];   // TRANSPOSED [t][4600][b]
__device__ __align__(16) float g_h2all[(size_t)NROW * EE];
__device__ __align__(16) float g_c[3][HH * BB];
__device__ __align__(16) float g_hf[3][HH * BB];
// A packs: single fp16 per weight, 8192 halves (16KB) per chunk, SW128-preswizzled
__device__ __align__(16) __half gA0[(size_t)36*18*8192];
__device__ __align__(16) __half gA1[(size_t)36*36*8192];
__device__ __align__(16) __half gA2[(size_t)13*25*8192];
// B packs: fp16 hi/lo, 4096 halves (8KB) per chunk
__device__ __align__(16) __half gB0[2][18*4096];
__device__ __align__(16) __half gB1[2][36*4096];
__device__ __align__(16) __half gB2[2][25*4096];
__device__ __align__(16) float gPart1[2][72*4096];   // parity double-buffered
__device__ __align__(16) float gPart2[2][26*4096];
__device__ int g_cA, g_cB, g_cC;   // monotonic per launch; reset at shutdown
__device__ int g_jbc[49];          // 36 L1 + 13 L2, monotonic
__device__ int g_end[3];           // shutdown handshake

template<int L> __device__ __forceinline__ __half* Apack(){
    return (L==0) ? gA0 : (L==1) ? gA1 : gA2;
}
template<int L> __device__ __forceinline__ __half* Bpack(int par){
    return (L==0) ? gB0[par] : (L==1) ? gB1[par] : gB2[par];
}

// ---------------- helpers ----------------
#define SWZ(x) ((x) ^ (((x) >> 3) & 0x70))
__device__ __forceinline__ uint32_t smem_u32(const void* p){
    uint32_t a;
    asm("{ .reg .u64 t; cvta.to.shared.u64 t, %1; cvt.u32.u64 %0, t; }" : "=r"(a) : "l"(p));
    return a;
}
__device__ __forceinline__ void cpa16(uint32_t dst, const void* src){
    asm volatile("cp.async.cg.shared.global [%0], [%1], 16;" :: "r"(dst), "l"(src));
}
#define CPA_COMMIT() asm volatile("cp.async.commit_group;" ::: "memory")
__device__ __forceinline__ int ld_acq(const int* p){
    int v; asm volatile("ld.acquire.gpu.b32 %0, [%1];" : "=r"(v) : "l"(p) : "memory");
    return v;
}
__device__ __forceinline__ float ldcg(const float* p){
    float v; asm volatile("ld.global.cg.f32 %0, [%1];" : "=f"(v) : "l"(p)); return v;
}
__device__ __forceinline__ void waitge(int* ctr, int target){
    if (threadIdx.x == 0){
        while (ld_acq(ctr) < target) __nanosleep(64);
    }
    __syncthreads();
}

// element-wise staging (init only)
__device__ __forceinline__ void stageB(__half* base, int kabs, int b, float v){
    int c = kabs >> 6, kk = kabs & 63;
    uint32_t pos = SWZ((uint32_t)(b*128 + kk*2)) >> 1;
    __half h = __float2half(v);
    base[(size_t)c*4096 + pos]        = h;
    base[(size_t)c*4096 + 2048 + pos] = __float2half(v - __half2float(h));
}

__device__ __forceinline__ void fma2(ull& d, ull a, ull b){
    asm("fma.rn.f32x2 %0, %1, %2, %0;" : "+l"(d) : "l"(a), "l"(b));
}
__device__ __forceinline__ ull dup2(float x){
    ull r; asm("mov.b64 %0, {%1, %2};" : "=l"(r) : "f"(x), "f"(x)); return r;
}
__device__ __forceinline__ float2 unp2(ull v){
    float2 r; asm("mov.b64 {%0, %1}, %2;" : "=f"(r.x), "=f"(r.y) : "l"(v)); return r;
}
__device__ __forceinline__ uint32_t pkhf(__half a, __half b){
    return (uint32_t)__half_as_ushort(a) | ((uint32_t)__half_as_ushort(b) << 16);
}

// =======================================================================
// fp32 SGEMM. MODE 0: gather + bias -> transposed g_P0. MODE 1: decoder.
// =======================================================================
template<int MODE>
__global__ __launch_bounds__(256) void sgemm_nt(
    const float* __restrict__ A, const int* __restrict__ gidx,
    const float* __restrict__ Bm, const float* __restrict__ bias,
    float* __restrict__ Cout, int N)
{
    const int K = EE;
    __shared__ __align__(16) float As[16][68];
    __shared__ __align__(16) float Bs[16][68];
    const float* Abase = (MODE==1) ? g_h2all : A;
    const int tid = threadIdx.x;
    const int bm = blockIdx.y*64, bn = blockIdx.x*64;
    const int r = tid>>2, q = tid&3;
    const float* arow = (MODE==0) ? Abase + (size_t)gidx[bm+r]*K : Abase + (size_t)(bm+r)*K;
    const int nrow = bn + r;
    const bool bok = nrow < N;
    const float* brow = Bm + (size_t)(bok ? nrow : (N-1))*K;
    const int tx = tid&15, ty = tid>>4;
    ull acc[4][2];
#pragma unroll
    for (int i=0;i<4;++i){ acc[i][0]=0ull; acc[i][1]=0ull; }
    for (int kc=0;kc<K;kc+=16){
        float4 av = *(const float4*)(arow + kc + q*4);
        float4 bv = *(const float4*)(brow + kc + q*4);
        if (!bok){ bv.x=bv.y=bv.z=bv.w=0.f; }
        __syncthreads();
        As[q*4+0][r]=av.x; As[q*4+1][r]=av.y; As[q*4+2][r]=av.z; As[q*4+3][r]=av.w;
        Bs[q*4+0][r]=bv.x; Bs[q*4+1][r]=bv.y; Bs[q*4+2][r]=bv.z; Bs[q*4+3][r]=bv.w;
        __syncthreads();
#pragma unroll
        for (int k=0;k<16;++k){
            ull b0 = *(const ull*)&Bs[k][tx*4];
            ull b1 = *(const ull*)&Bs[k][tx*4+2];
            float4 a4 = *(const float4*)&As[k][ty*4];
            ull a;
            a=dup2(a4.x); fma2(acc[0][0],a,b0); fma2(acc[0][1],a,b1);
            a=dup2(a4.y); fma2(acc[1][0],a,b0); fma2(acc[1][1],a,b1);
            a=dup2(a4.z); fma2(acc[2][0],a,b0); fma2(acc[2][1],a,b1);
            a=dup2(a4.w); fma2(acc[3][0],a,b0); fma2(acc[3][1],a,b1);
        }
    }
    if constexpr (MODE == 0){
        __shared__ float Ts[64][65];
        __syncthreads();
#pragma unroll
        for (int i=0;i<4;++i){
            float2 c0=unp2(acc[i][0]), c1=unp2(acc[i][1]);
            float v[4]={c0.x,c0.y,c1.x,c1.y};
#pragma unroll
            for (int j=0;j<4;++j){
                int col = bn + tx*4 + j;
                Ts[ty*4+i][tx*4+j] = v[j] + (col < N ? bias[col] : 0.f);
            }
        }
        __syncthreads();
        for (int idx=tid; idx<4096; idx+=256){
            int cl = idx>>6, rl = idx&63;
            int col = bn + cl;
            if (col < N){
                int row = bm + rl;
                int t = row>>5, b = row&31;
                g_P0[((size_t)t*M4H + col)*32 + b] = Ts[rl][cl];
            }
        }
    } else {
#pragma unroll
        for (int i=0;i<4;++i){
            int row = bm + ty*4 + i;
            float2 c0=unp2(acc[i][0]), c1=unp2(acc[i][1]);
            float v[4]={c0.x,c0.y,c1.x,c1.y};
#pragma unroll
            for (int j=0;j<4;++j){
                int col = bn + tx*4 + j;
                if (col < N) Cout[(size_t)row*N + col] = v[j] + bias[col];
            }
        }
    }
}

// =======================================================================
// A-pack prep: single fp16, gate-interleaved, SW128-preswizzled
// =======================================================================
template<int L>
__global__ void prep_A(const float* __restrict__ Wi, const float* __restrict__ Wh)
{
    using C = LC<L>;
    const int KXP = (L==0) ? 0 : 1152;
    size_t idx = (size_t)blockIdx.x*256 + threadIdx.x;
    size_t total = (size_t)C::NJB*C::NCH*8192;
    if (idx >= total) return;
    int kk  = (int)(idx & 63);
    int row = (int)((idx>>6) & 127);
    int ch  = (int)((idx>>13) % C::NCH);
    int jb  = (int)(idx / ((size_t)C::NCH*8192));
    int gate = row>>5, j = jb*32 + (row&31);
    int kabs = ch*64 + kk;
    float v = 0.f;
    if (j < C::OUT){
        if (L != 0 && kabs < 1150)
            v = Wi[(size_t)(gate*C::OUT + j)*1150 + kabs];
        else if (kabs >= KXP && kabs - KXP < C::KH)
            v = Wh[(size_t)(gate*C::OUT + j)*C::KH + (kabs - KXP)];
    }
    uint32_t pos = SWZ((uint32_t)(row*128 + kk*2)) >> 1;
    __half* Ap = Apack<L>() + (size_t)(jb*C::NCH + ch)*8192;
    Ap[pos] = __float2half(v);
}

// =======================================================================
// MMA over a chunk list (4-deep cp.async pipeline, 2 fp16 passes:
// A_fp16 x B_hi + A_fp16 x B_lo). Stage = A 16KB + B 8KB = 24KB.
// =======================================================================
#define STGB 24576
#define SMEM_MMA (4*STGB)

__device__ __forceinline__ void mma_chunks(
    uint32_t sb, const __half* Ab, const __half* Bb,
    const int* cl, int cnt, float (&acc)[2][4][4])
{
    if (cnt <= 0) return;
    const int tid = threadIdx.x;
    const int w = tid>>5, ln = tid&31;
    const int arow = w*32 + (ln&7) + ((ln>>3)&1)*8;
    const int akad = ((ln>>4)&1)*16;
    const int brow = ((ln>>4)&1)*8 + (ln&7);
    const int bkad = ((ln>>3)&1)*16;

    auto fill = [&](int i){
        uint32_t dst = sb + (i & 3)*STGB;
        int c = cl[i];
        const char* a = (const char*)(Ab + (size_t)c*8192);
#pragma unroll
        for (int r=0;r<8;r++) cpa16(dst + r*2048 + tid*16, a + r*2048 + tid*16);
        const char* b = (const char*)(Bb + (size_t)c*4096);
#pragma unroll
        for (int r=0;r<4;r++) cpa16(dst + 16384 + r*2048 + tid*16, b + r*2048 + tid*16);
    };
    for (int i=0;i<4;i++){ if (i<cnt) fill(i); CPA_COMMIT(); }

    for (int i=0;i<cnt;i++){
        asm volatile("cp.async.wait_group 3;" ::: "memory");
        __syncthreads();
        uint32_t so = sb + (i & 3)*STGB;
#pragma unroll
        for (int p=0;p<2;p++){
            uint32_t aoff = so;
            uint32_t boff = so + 16384u + (p ? 4096u : 0u);
#pragma unroll
            for (int ks=0;ks<4;ks++){
                const int kb = ks*32;
                uint32_t bf[8];
                uint32_t ba0 = boff + SWZ((uint32_t)(brow*128 + kb + bkad));
                uint32_t ba1 = boff + SWZ((uint32_t)((brow+16)*128 + kb + bkad));
                asm volatile("ldmatrix.sync.aligned.m8n8.x4.shared.b16 {%0,%1,%2,%3}, [%4];"
                    : "=r"(bf[0]),"=r"(bf[1]),"=r"(bf[2]),"=r"(bf[3]) : "r"(ba0));
                asm volatile("ldmatrix.sync.aligned.m8n8.x4.shared.b16 {%0,%1,%2,%3}, [%4];"
                    : "=r"(bf[4]),"=r"(bf[5]),"=r"(bf[6]),"=r"(bf[7]) : "r"(ba1));
#pragma unroll
                for (int mi=0;mi<2;mi++){
                    uint32_t af[4];
                    uint32_t aa = aoff + SWZ((uint32_t)((arow+mi*16)*128 + kb + akad));
                    asm volatile("ldmatrix.sync.aligned.m8n8.x4.shared.b16 {%0,%1,%2,%3}, [%4];"
                        : "=r"(af[0]),"=r"(af[1]),"=r"(af[2]),"=r"(af[3]) : "r"(aa));
#pragma unroll
                    for (int ni=0;ni<4;ni++){
                        asm volatile(
                            "mma.sync.aligned.m16n8k16.row.col.f32.f16.f16.f32 "
                            "{%0,%1,%2,%3}, {%4,%5,%6,%7}, {%8,%9}, {%0,%1,%2,%3};"
                            : "+f"(acc[mi][ni][0]),"+f"(acc[mi][ni][1]),
                              "+f"(acc[mi][ni][2]),"+f"(acc[mi][ni][3])
                            : "r"(af[0]),"r"(af[1]),"r"(af[2]),"r"(af[3]),
                              "r"(bf[ni*2]),"r"(bf[ni*2+1]));
                    }
                }
            }
        }
        __syncthreads();
        if (i+4 < cnt) fill(i+4);
        CPA_COMMIT();
    }
}

// =======================================================================
// One layer-step for a dedicated CTA (spatial pipeline stage)
// =======================================================================
template<int L>
__device__ __forceinline__ void step_layer(
    char* sm, const float* __restrict__ bx, const float* __restrict__ bhh,
    int t, int jb, int s)
{
    using C = LC<L>;
    const int tid = threadIdx.x;
    const int par = t & 1;
    uint32_t sb = smem_u32(sm);
    const __half* Ab = Apack<L>() + (size_t)jb*C::NCH*8192;
    const __half* Bb = Bpack<L>(par);

    float acc[2][4][4];
#pragma unroll
    for (int mi=0;mi<2;mi++)
#pragma unroll
        for (int ni=0;ni<4;ni++)
#pragma unroll
            for (int q=0;q<4;q++) acc[mi][ni][q]=0.f;

    int l1[18], l2[9]; int n1=0, n2=0;
    if (L == 0){
        for (int c=0;c<18;c++) l1[n1++]=c;
    } else if (L == 1){
        for (int c=18;c<36;c++) if ((c&1)==s) l1[n1++]=c;
        for (int c=0;c<18;c++)  if ((c&1)==s) l2[n2++]=c;
    } else {
        for (int c=18;c<25;c++) if ((c&1)==s) l1[n1++]=c;
        for (int c=0;c<18;c++)  if ((c&1)==s) l2[n2++]=c;
    }

    if (L == 0)      waitge(&g_cA, NT0*t);
    else if (L == 1) waitge(&g_cB, NT1*t);
    else             waitge(&g_cC, NT2*t);
    mma_chunks(sb, Ab, Bb, l1, n1, acc);
    if (L == 1){ waitge(&g_cA, NT0*(t+1)); mma_chunks(sb, Ab, Bb, l2, n2, acc); }
    if (L == 2){ waitge(&g_cB, NT1*(t+1)); mma_chunks(sb, Ab, Bb, l2, n2, acc); }

    // ---- partials ----
    const int w = tid>>5, ln = tid&31;
    __syncthreads();
    if (L == 0){
        float* sacc = (float*)sm;     // aliases stage buffers (idle now)
#pragma unroll
        for (int mi=0;mi<2;mi++){
            int row = w*32 + mi*16 + (ln>>2);
#pragma unroll
            for (int ni=0;ni<4;ni++){
                int col = ni*8 + (ln&3)*2;
                *(float2*)(sacc + row*32 + col)     = make_float2(acc[mi][ni][0], acc[mi][ni][1]);
                *(float2*)(sacc + (row+8)*32 + col) = make_float2(acc[mi][ni][2], acc[mi][ni][3]);
            }
        }
        __syncthreads();
    } else {
        float* P = ((L==1) ? gPart1[par] : gPart2[par]) + (size_t)(jb*2+s)*4096;
#pragma unroll
        for (int mi=0;mi<2;mi++){
            int row = w*32 + mi*16 + (ln>>2);
#pragma unroll
            for (int ni=0;ni<4;ni++){
                int col = ni*8 + (ln&3)*2;
                *(float2*)(P + row*32 + col)     = make_float2(acc[mi][ni][0], acc[mi][ni][1]);
                *(float2*)(P + (row+8)*32 + col) = make_float2(acc[mi][ni][2], acc[mi][ni][3]);
            }
        }
        __threadfence();
        __syncthreads();
        int* jc = &g_jbc[((L==1) ? 0 : 36) + jb];
        if (tid == 0){
            atomicAdd(jc, 1);
            while (ld_acq(jc) < 2*(t+1)) __nanosleep(64);
        }
        __syncthreads();
    }

    // ---- backpressure: downstream must have consumed the buffer we are
    // about to overwrite (step t-2's x staging). Acyclic: guards reference
    // strictly earlier steps. ----
    if (L == 0 && t >= 2) waitge(&g_cB, NT1*(t-1));
    if (L == 1 && t >= 2) waitge(&g_cC, NT2*(t-1));

    // ---- pointwise on this CTA's j-slice ----
    constexpr int JS = (L==0) ? 32 : 16;
    const int j0 = jb*32 + s*JS;
    __half* shi = (__half*)(sm + 16384);
    __half* slo = (__half*)(sm + 20608);
    float*  sf  = (float*)(sm + 24832);
    float* cst = g_c[L];
    constexpr int IT = JS*32/128;
#pragma unroll
    for (int it=0; it<IT; ++it){
        int item = tid + it*128;
        int ljj = item>>5, b = item&31;
        int j = j0 + ljj;
        int jj = s*JS + ljj;
        float hv = 0.f;
        if (j < C::OUT){
            float pre[4];
            if (L == 0){
                const float* sacc = (const float*)sm;
#pragma unroll
                for (int g=0; g<4; ++g) pre[g] = sacc[(g*32+jj)*32 + b];
            } else {
                const float* Pb = ((L==1) ? gPart1[par] : gPart2[par]) + (size_t)jb*2*4096;
#pragma unroll
                for (int g=0; g<4; ++g)
                    pre[g] = ldcg(Pb + (g*32+jj)*32 + b) + ldcg(Pb + 4096 + (g*32+jj)*32 + b);
            }
            float ip, fp, op, gp;
            if (L == 0){
                const float* p0 = g_P0 + ((size_t)t*M4H)*32 + b;
                ip = pre[0] + p0[(size_t)(j       )*32] + bhh[j];
                fp = pre[1] + p0[(size_t)(HH   + j)*32] + bhh[HH + j];
                op = pre[2] + p0[(size_t)(2*HH + j)*32] + bhh[2*HH + j];
                gp = pre[3] + p0[(size_t)(3*HH + j)*32] + bhh[3*HH + j];
            } else {
                ip = pre[0] + bx[j]            + bhh[j];
                fp = pre[1] + bx[C::OUT + j]   + bhh[C::OUT + j];
                op = pre[2] + bx[2*C::OUT + j] + bhh[2*C::OUT + j];
                gp = pre[3] + bx[3*C::OUT + j] + bhh[3*C::OUT + j];
            }
            float gi=1.f/(1.f+expf(-ip)), gf=1.f/(1.f+expf(-fp));
            float go=1.f/(1.f+expf(-op)), gg=tanhf(gp);
            float cn = gf*cst[j*32+b] + gi*gg;
            cst[j*32+b] = cn;
            hv = go*tanhf(cn);
            g_hf[L][j*32+b] = hv;
        }
        __half hbf = __float2half(hv);
        shi[ljj*33+b] = hbf;
        slo[ljj*33+b] = __float2half(hv - __half2float(hbf));
        if (L == 2) sf[ljj*33+b] = hv;
    }
    __syncthreads();

    // ---- packed staging stores ----
    constexpr int NBLK = JS/8;
    if (L != 2){
        const int total = 2*32*NBLK;
        for (int idx=tid; idx<total; idx+=128){
            int tgt = idx / (32*NBLK);
            int rem = idx % (32*NBLK);
            int b = rem & 31, bq = rem >> 5;
            __half* base; int kabs0;
            if (L == 0){ base = tgt ? gB1[par] : gB0[par^1]; kabs0 = j0; }
            else       { base = tgt ? gB2[par] : gB1[par^1]; kabs0 = tgt ? j0 : 1152 + j0; }
            int kabs = kabs0 + bq*8;
            int c = kabs >> 6, kk = kabs & 63;
            size_t pos = (size_t)c*4096 + (SWZ((uint32_t)(b*128 + kk*2)) >> 1);
            int r0 = bq*8;
            uint4 qh = make_uint4(
                pkhf(shi[(r0+0)*33+b], shi[(r0+1)*33+b]),
                pkhf(shi[(r0+2)*33+b], shi[(r0+3)*33+b]),
                pkhf(shi[(r0+4)*33+b], shi[(r0+5)*33+b]),
                pkhf(shi[(r0+6)*33+b], shi[(r0+7)*33+b]));
            uint4 ql = make_uint4(
                pkhf(slo[(r0+0)*33+b], slo[(r0+1)*33+b]),
                pkhf(slo[(r0+2)*33+b], slo[(r0+3)*33+b]),
                pkhf(slo[(r0+4)*33+b], slo[(r0+5)*33+b]),
                pkhf(slo[(r0+6)*33+b], slo[(r0+7)*33+b]));
            *(uint4*)(base + pos)        = qh;
            *(uint4*)(base + pos + 2048) = ql;
        }
    } else {
        if (tid < 64 && j0 < C::OUT){
            int b = tid & 31, bq = tid >> 5;
            int kabs = 1152 + j0 + bq*8;
            int c = kabs >> 6, kk = kabs & 63;
            size_t pos = (size_t)c*4096 + (SWZ((uint32_t)(b*128 + kk*2)) >> 1);
            int r0 = bq*8;
            uint4 qh = make_uint4(
                pkhf(shi[(r0+0)*33+b], shi[(r0+1)*33+b]),
                pkhf(shi[(r0+2)*33+b], shi[(r0+3)*33+b]),
                pkhf(shi[(r0+4)*33+b], shi[(r0+5)*33+b]),
                pkhf(shi[(r0+6)*33+b], shi[(r0+7)*33+b]));
            uint4 ql = make_uint4(
                pkhf(slo[(r0+0)*33+b], slo[(r0+1)*33+b]),
                pkhf(slo[(r0+2)*33+b], slo[(r0+3)*33+b]),
                pkhf(slo[(r0+4)*33+b], slo[(r0+5)*33+b]),
                pkhf(slo[(r0+6)*33+b], slo[(r0+7)*33+b]));
            __half* base = gB2[par^1];
            *(uint4*)(base + pos)        = qh;
            *(uint4*)(base + pos + 2048) = ql;
        }
        {
            int b = tid & 31, bq = tid >> 5;
            if (tid < 128 && j0 < C::OUT){
                float4 f = make_float4(sf[(bq*4+0)*33+b], sf[(bq*4+1)*33+b],
                                       sf[(bq*4+2)*33+b], sf[(bq*4+3)*33+b]);
                *(float4*)(g_h2all + (size_t)(t*32 + b)*EE + j0 + bq*4) = f;
            }
        }
    }

    __threadfence();
    __syncthreads();
    if (tid == 0){
        if (L == 0)      atomicAdd(&g_cA, 1);
        else if (L == 1) atomicAdd(&g_cB, 1);
        else             atomicAdd(&g_cC, 1);
    }
}

// =======================================================================
// Persistent spatially-pipelined recurrence: 36 L0 + 72 L1 + 26 L2 CTAs
// =======================================================================
__global__ __launch_bounds__(128) void recurrence(
    const float* __restrict__ bh0,
    const float* __restrict__ bi1, const float* __restrict__ bh1,
    const float* __restrict__ bi2, const float* __restrict__ bh2)
{
    extern __shared__ __align__(128) char sm[];
    const int blk = blockIdx.x;

    if (blk < NT0){
        for (int t=0; t<TT; ++t) step_layer<0>(sm, nullptr, bh0, t, blk, 0);
    } else if (blk < NT0 + NT1){
        int r = blk - NT0;
        for (int t=0; t<TT; ++t) step_layer<1>(sm, bi1, bh1, t, r>>1, r&1);
    } else {
        int r = blk - NT0 - NT1;
        for (int t=0; t<TT; ++t) step_layer<2>(sm, bi2, bh2, t, r>>1, r&1);
    }

    // ---- replay-safe shutdown: reset all counters ----
    __syncthreads();
    if (threadIdx.x == 0){
        atomicAdd(&g_end[0], 1);
        if (blk == 0){
            while (ld_acq(&g_end[0]) < NTOT) __nanosleep(128);
            g_cA = 0; g_cB = 0; g_cC = 0;
            for (int i=0;i<49;i++) g_jbc[i] = 0;
            g_end[0] = 0;
            __threadfence();
            atomicExch(&g_end[1], 1);
            while (ld_acq(&g_end[2]) < NTOT-1) __nanosleep(128);
            g_end[2] = 0;
            __threadfence();
            atomicExch(&g_end[1], 0);
        } else {
            while (ld_acq(&g_end[1]) == 0) __nanosleep(128);
            atomicAdd(&g_end[2], 1);
        }
    }
}

// ---- init / finalize ----
__global__ void init_states(const float* __restrict__ h0,
                            const float* __restrict__ c0,
                            const float* __restrict__ h0l,
                            const float* __restrict__ c0l)
{
    int idx = blockIdx.x*blockDim.x + threadIdx.x;
    if (idx < HH*BB){
        int k = idx>>5, b = idx&31;
        g_c[0][idx] = c0[b*HH + k];
        g_c[1][idx] = c0[BB*HH + b*HH + k];
        stageB(gB0[0], k,        b, h0[b*HH + k]);
        stageB(gB1[0], 1152 + k, b, h0[BB*HH + b*HH + k]);
    }
    if (idx < EE*BB){
        int k = idx>>5, b = idx&31;
        g_c[2][idx] = c0l[b*EE + k];
        stageB(gB2[0], 1152 + k, b, h0l[b*EE + k]);
    }
}

__global__ void finalize_states(float* __restrict__ out)
{
    const size_t D1 = (size_t)TT*BB*VV;
    const size_t D2 = D1 + 2*BB*HH;
    const size_t D3 = D2 + BB*EE;
    const size_t D4 = D3 + 2*BB*HH;
    int idx = blockIdx.x*blockDim.x + threadIdx.x;
    if (idx < HH*BB){
        int k = idx>>5, b = idx&31;
        out[D1 + b*HH + k]           = g_hf[0][idx];
        out[D1 + BB*HH + b*HH + k]   = g_hf[1][idx];
        out[D3 + b*HH + k]           = g_c[0][idx];
        out[D3 + BB*HH + b*HH + k]   = g_c[1][idx];
    }
    if (idx < EE*BB){
        int k = idx>>5, b = idx&31;
        out[D2 + b*EE + k] = g_hf[2][idx];
        out[D4 + b*EE + k] = g_c[2][idx];
    }
}

// =======================================================================
extern "C" void kernel_launch(void* const* d_in, const int* in_sizes, int n_in,
                              void* d_out, int out_size)
{
    const int*   x    = (const int*)  d_in[0];
    const float* h0   = (const float*)d_in[1];
    const float* c0   = (const float*)d_in[2];
    const float* h0l  = (const float*)d_in[3];
    const float* c0l  = (const float*)d_in[4];
    const float* emb  = (const float*)d_in[5];
    const float* Wi0  = (const float*)d_in[6];
    const float* bi0  = (const float*)d_in[7];
    const float* Wh0  = (const float*)d_in[8];
    const float* bh0  = (const float*)d_in[9];
    const float* Wi1  = (const float*)d_in[10];
    const float* bi1  = (const float*)d_in[11];
    const float* Wh1  = (const float*)d_in[12];
    const float* bh1  = (const float*)d_in[13];
    const float* Wi2  = (const float*)d_in[14];
    const float* bi2  = (const float*)d_in[15];
    const float* Wh2  = (const float*)d_in[16];
    const float* bh2  = (const float*)d_in[17];
    const float* decW = (const float*)d_in[18];
    const float* decb = (const float*)d_in[19];
    float* out = (float*)d_out;

    cudaFuncSetAttribute(recurrence, cudaFuncAttributeMaxDynamicSharedMemorySize, SMEM_MMA);

    init_states<<<(HH*BB + 255)/256, 256>>>(h0, c0, h0l, c0l);

    prep_A<0><<<(36*18*8192 + 255)/256, 256>>>(nullptr, Wh0);
    prep_A<1><<<(36*36*8192 + 255)/256, 256>>>(Wi1, Wh1);
    prep_A<2><<<(13*25*8192 + 255)/256, 256>>>(Wi2, Wh2);

    {   // P0 = emb[x] @ Wi0^T + bi0 (written transposed [t][col][b])
        dim3 g((M4H + 63)/64, NROW/64);
        sgemm_nt<0><<<g, 256>>>(emb, x, Wi0, bi0, nullptr, M4H);
    }

    recurrence<<<NTOT, 128, SMEM_MMA>>>(bh0, bi1, bh1, bi2, bh2);

    {   // decoder
        dim3 g((VV + 63)/64, NROW/64);
        sgemm_nt<1><<<g, 256>>>(nullptr, nullptr, decW, decb, out, VV);
    }

    finalize_states<<<(HH*BB + 255)/256, 256>>>(out);
}

// round 17
// speedup vs baseline: 2.3579x; 1.1241x over previous
#include <cuda_runtime.h>
#include <cuda_bf16.h>
#include <cuda_fp16.h>
#include <math.h>
#include <stdint.h>

#define EE   400
#define HH   1150
#define VV   10000
#define TT   256
#define BB   32
#define M4H  4600
#define NROW 8192
#define NT0  36
#define NT1  72
#define NT2  26
#define NTOT 134
typedef unsigned long long ull;

template<int L> struct LC;
template<> struct LC<0>{ enum{OUT=1150,NJB=36,NCH=18,S=1,KH=1150}; };
template<> struct LC<1>{ enum{OUT=1150,NJB=36,NCH=36,S=2,KH=1150}; };
template<> struct LC<2>{ enum{OUT=400, NJB=13,NCH=25,S=2,KH=400 }; };

// ---------------- device scratch ----------------
__device__ __align__(16) float g_P0[(size_t)NROW * M4H];   // TRANSPOSED [t][4600][b]
__device__ __align__(16) float g_h2all[(size_t)NROW * EE];
__device__ __align__(16) float g_c[3][HH * BB];
__device__ __align__(16) float g_hf[3][HH * BB];
// A packs: single fp16 per weight, 8192 halves (16KB) per chunk, SW128-preswizzled
__device__ __align__(16) __half gA0[(size_t)36*18*8192];
__device__ __align__(16) __half gA1[(size_t)36*36*8192];
__device__ __align__(16) __half gA2[(size_t)13*25*8192];
// B packs: fp16 hi/lo, 4096 halves (8KB) per chunk
__device__ __align__(16) __half gB0[2][18*4096];
__device__ __align__(16) __half gB1[2][36*4096];
__device__ __align__(16) __half gB2[2][25*4096];
__device__ __align__(16) float gPart1[2][72*4096];   // parity double-buffered
__device__ __align__(16) float gPart2[2][26*4096];
__device__ int g_cA, g_cB, g_cC;   // monotonic per launch; reset at shutdown
__device__ int g_jbc[49];          // 36 L1 + 13 L2, monotonic
__device__ int g_end[3];           // shutdown handshake

template<int L> __device__ __forceinline__ __half* Apack(){
    return (L==0) ? gA0 : (L==1) ? gA1 : gA2;
}
template<int L> __device__ __forceinline__ __half* Bpack(int par){
    return (L==0) ? gB0[par] : (L==1) ? gB1[par] : gB2[par];
}

// ---------------- helpers ----------------
#define SWZ(x) ((x) ^ (((x) >> 3) & 0x70))
__device__ __forceinline__ uint32_t smem_u32(const void* p){
    uint32_t a;
    asm("{ .reg .u64 t; cvta.to.shared.u64 t, %1; cvt.u32.u64 %0, t; }" : "=r"(a) : "l"(p));
    return a;
}
__device__ __forceinline__ void cpa16(uint32_t dst, const void* src){
    asm volatile("cp.async.cg.shared.global [%0], [%1], 16;" :: "r"(dst), "l"(src));
}
#define CPA_COMMIT() asm volatile("cp.async.commit_group;" ::: "memory")
__device__ __forceinline__ int ld_acq(const int* p){
    int v; asm volatile("ld.acquire.gpu.b32 %0, [%1];" : "=r"(v) : "l"(p) : "memory");
    return v;
}
__device__ __forceinline__ float ldcg(const float* p){
    float v; asm volatile("ld.global.cg.f32 %0, [%1];" : "=f"(v) : "l"(p)); return v;
}
__device__ __forceinline__ void waitge(int* ctr, int target){
    if (threadIdx.x == 0){
        while (ld_acq(ctr) < target) __nanosleep(32);
    }
    __syncthreads();
}

// element-wise staging (init only)
__device__ __forceinline__ void stageB(__half* base, int kabs, int b, float v){
    int c = kabs >> 6, kk = kabs & 63;
    uint32_t pos = SWZ((uint32_t)(b*128 + kk*2)) >> 1;
    __half h = __float2half(v);
    base[(size_t)c*4096 + pos]        = h;
    base[(size_t)c*4096 + 2048 + pos] = __float2half(v - __half2float(h));
}

__device__ __forceinline__ void fma2(ull& d, ull a, ull b){
    asm("fma.rn.f32x2 %0, %1, %2, %0;" : "+l"(d) : "l"(a), "l"(b));
}
__device__ __forceinline__ ull dup2(float x){
    ull r; asm("mov.b64 %0, {%1, %2};" : "=l"(r) : "f"(x), "f"(x)); return r;
}
__device__ __forceinline__ float2 unp2(ull v){
    float2 r; asm("mov.b64 {%0, %1}, %2;" : "=f"(r.x), "=f"(r.y) : "l"(v)); return r;
}
__device__ __forceinline__ uint32_t pkhf(__half a, __half b){
    return (uint32_t)__half_as_ushort(a) | ((uint32_t)__half_as_ushort(b) << 16);
}

// =======================================================================
// fp32 SGEMM. MODE 0: gather + bias -> transposed g_P0. MODE 1: decoder.
// =======================================================================
template<int MODE>
__global__ __launch_bounds__(256) void sgemm_nt(
    const float* __restrict__ A, const int* __restrict__ gidx,
    const float* __restrict__ Bm, const float* __restrict__ bias,
    float* __restrict__ Cout, int N)
{
    const int K = EE;
    __shared__ __align__(16) float As[16][68];
    __shared__ __align__(16) float Bs[16][68];
    const float* Abase = (MODE==1) ? g_h2all : A;
    const int tid = threadIdx.x;
    const int bm = blockIdx.y*64, bn = blockIdx.x*64;
    const int r = tid>>2, q = tid&3;
    const float* arow = (MODE==0) ? Abase + (size_t)gidx[bm+r]*K : Abase + (size_t)(bm+r)*K;
    const int nrow = bn + r;
    const bool bok = nrow < N;
    const float* brow = Bm + (size_t)(bok ? nrow : (N-1))*K;
    const int tx = tid&15, ty = tid>>4;
    ull acc[4][2];
#pragma unroll
    for (int i=0;i<4;++i){ acc[i][0]=0ull; acc[i][1]=0ull; }
    for (int kc=0;kc<K;kc+=16){
        float4 av = *(const float4*)(arow + kc + q*4);
        float4 bv = *(const float4*)(brow + kc + q*4);
        if (!bok){ bv.x=bv.y=bv.z=bv.w=0.f; }
        __syncthreads();
        As[q*4+0][r]=av.x; As[q*4+1][r]=av.y; As[q*4+2][r]=av.z; As[q*4+3][r]=av.w;
        Bs[q*4+0][r]=bv.x; Bs[q*4+1][r]=bv.y; Bs[q*4+2][r]=bv.z; Bs[q*4+3][r]=bv.w;
        __syncthreads();
#pragma unroll
        for (int k=0;k<16;++k){
            ull b0 = *(const ull*)&Bs[k][tx*4];
            ull b1 = *(const ull*)&Bs[k][tx*4+2];
            float4 a4 = *(const float4*)&As[k][ty*4];
            ull a;
            a=dup2(a4.x); fma2(acc[0][0],a,b0); fma2(acc[0][1],a,b1);
            a=dup2(a4.y); fma2(acc[1][0],a,b0); fma2(acc[1][1],a,b1);
            a=dup2(a4.z); fma2(acc[2][0],a,b0); fma2(acc[2][1],a,b1);
            a=dup2(a4.w); fma2(acc[3][0],a,b0); fma2(acc[3][1],a,b1);
        }
    }
    if constexpr (MODE == 0){
        __shared__ float Ts[64][65];
        __syncthreads();
#pragma unroll
        for (int i=0;i<4;++i){
            float2 c0=unp2(acc[i][0]), c1=unp2(acc[i][1]);
            float v[4]={c0.x,c0.y,c1.x,c1.y};
#pragma unroll
            for (int j=0;j<4;++j){
                int col = bn + tx*4 + j;
                Ts[ty*4+i][tx*4+j] = v[j] + (col < N ? bias[col] : 0.f);
            }
        }
        __syncthreads();
        for (int idx=tid; idx<4096; idx+=256){
            int cl = idx>>6, rl = idx&63;
            int col = bn + cl;
            if (col < N){
                int row = bm + rl;
                int t = row>>5, b = row&31;
                g_P0[((size_t)t*M4H + col)*32 + b] = Ts[rl][cl];
            }
        }
    } else {
#pragma unroll
        for (int i=0;i<4;++i){
            int row = bm + ty*4 + i;
            float2 c0=unp2(acc[i][0]), c1=unp2(acc[i][1]);
            float v[4]={c0.x,c0.y,c1.x,c1.y};
#pragma unroll
            for (int j=0;j<4;++j){
                int col = bn + tx*4 + j;
                if (col < N) Cout[(size_t)row*N + col] = v[j] + bias[col];
            }
        }
    }
}

// =======================================================================
// A-pack prep: single fp16, gate-interleaved, SW128-preswizzled
// =======================================================================
template<int L>
__global__ void prep_A(const float* __restrict__ Wi, const float* __restrict__ Wh)
{
    using C = LC<L>;
    const int KXP = (L==0) ? 0 : 1152;
    size_t idx = (size_t)blockIdx.x*256 + threadIdx.x;
    size_t total = (size_t)C::NJB*C::NCH*8192;
    if (idx >= total) return;
    int kk  = (int)(idx & 63);
    int row = (int)((idx>>6) & 127);
    int ch  = (int)((idx>>13) % C::NCH);
    int jb  = (int)(idx / ((size_t)C::NCH*8192));
    int gate = row>>5, j = jb*32 + (row&31);
    int kabs = ch*64 + kk;
    float v = 0.f;
    if (j < C::OUT){
        if (L != 0 && kabs < 1150)
            v = Wi[(size_t)(gate*C::OUT + j)*1150 + kabs];
        else if (kabs >= KXP && kabs - KXP < C::KH)
            v = Wh[(size_t)(gate*C::OUT + j)*C::KH + (kabs - KXP)];
    }
    uint32_t pos = SWZ((uint32_t)(row*128 + kk*2)) >> 1;
    __half* Ap = Apack<L>() + (size_t)(jb*C::NCH + ch)*8192;
    Ap[pos] = __float2half(v);
}

// =======================================================================
// MMA over a chunk list. 256 threads = 8 warps; warp w owns M16 rows
// [w*16, w*16+16). 4-deep cp.async pipeline, 2 fp16 passes (B hi + lo).
// =======================================================================
#define STGB 24576
#define SMEM_MMA (4*STGB)

__device__ __forceinline__ void mma_chunks(
    uint32_t sb, const __half* Ab, const __half* Bb,
    const int* cl, int cnt, float (&acc)[4][4])
{
    if (cnt <= 0) return;
    const int tid = threadIdx.x;
    const int w = tid>>5, ln = tid&31;
    const int arow = w*16 + (ln&7) + ((ln>>3)&1)*8;
    const int akad = ((ln>>4)&1)*16;
    const int brow = ((ln>>4)&1)*8 + (ln&7);
    const int bkad = ((ln>>3)&1)*16;

    auto fill = [&](int i){
        uint32_t dst = sb + (i & 3)*STGB;
        int c = cl[i];
        const char* a = (const char*)(Ab + (size_t)c*8192);
#pragma unroll
        for (int r=0;r<4;r++) cpa16(dst + r*4096 + tid*16, a + r*4096 + tid*16);
        const char* b = (const char*)(Bb + (size_t)c*4096);
#pragma unroll
        for (int r=0;r<2;r++) cpa16(dst + 16384 + r*4096 + tid*16, b + r*4096 + tid*16);
    };
    for (int i=0;i<4;i++){ if (i<cnt) fill(i); CPA_COMMIT(); }

    for (int i=0;i<cnt;i++){
        asm volatile("cp.async.wait_group 3;" ::: "memory");
        __syncthreads();
        uint32_t so = sb + (i & 3)*STGB;
#pragma unroll
        for (int p=0;p<2;p++){
            uint32_t aoff = so;
            uint32_t boff = so + 16384u + (p ? 4096u : 0u);
#pragma unroll
            for (int ks=0;ks<4;ks++){
                const int kb = ks*32;
                uint32_t bf[8];
                uint32_t ba0 = boff + SWZ((uint32_t)(brow*128 + kb + bkad));
                uint32_t ba1 = boff + SWZ((uint32_t)((brow+16)*128 + kb + bkad));
                asm volatile("ldmatrix.sync.aligned.m8n8.x4.shared.b16 {%0,%1,%2,%3}, [%4];"
                    : "=r"(bf[0]),"=r"(bf[1]),"=r"(bf[2]),"=r"(bf[3]) : "r"(ba0));
                asm volatile("ldmatrix.sync.aligned.m8n8.x4.shared.b16 {%0,%1,%2,%3}, [%4];"
                    : "=r"(bf[4]),"=r"(bf[5]),"=r"(bf[6]),"=r"(bf[7]) : "r"(ba1));
                uint32_t af[4];
                uint32_t aa = aoff + SWZ((uint32_t)(arow*128 + kb + akad));
                asm volatile("ldmatrix.sync.aligned.m8n8.x4.shared.b16 {%0,%1,%2,%3}, [%4];"
                    : "=r"(af[0]),"=r"(af[1]),"=r"(af[2]),"=r"(af[3]) : "r"(aa));
#pragma unroll
                for (int ni=0;ni<4;ni++){
                    asm volatile(
                        "mma.sync.aligned.m16n8k16.row.col.f32.f16.f16.f32 "
                        "{%0,%1,%2,%3}, {%4,%5,%6,%7}, {%8,%9}, {%0,%1,%2,%3};"
                        : "+f"(acc[ni][0]),"+f"(acc[ni][1]),
                          "+f"(acc[ni][2]),"+f"(acc[ni][3])
                        : "r"(af[0]),"r"(af[1]),"r"(af[2]),"r"(af[3]),
                          "r"(bf[ni*2]),"r"(bf[ni*2+1]));
                }
            }
        }
        __syncthreads();
        if (i+4 < cnt) fill(i+4);
        CPA_COMMIT();
    }
}

// =======================================================================
// One layer-step for a dedicated CTA (spatial pipeline stage)
// =======================================================================
template<int L>
__device__ __forceinline__ void step_layer(
    char* sm, const float* __restrict__ bx, const float* __restrict__ bhh,
    int t, int jb, int s)
{
    using C = LC<L>;
    const int tid = threadIdx.x;
    const int par = t & 1;
    uint32_t sb = smem_u32(sm);
    const __half* Ab = Apack<L>() + (size_t)jb*C::NCH*8192;
    const __half* Bb = Bpack<L>(par);

    float acc[4][4];
#pragma unroll
    for (int ni=0;ni<4;ni++)
#pragma unroll
        for (int q=0;q<4;q++) acc[ni][q]=0.f;

    int l1[18], l2[9]; int n1=0, n2=0;
    if (L == 0){
        for (int c=0;c<18;c++) l1[n1++]=c;
    } else if (L == 1){
        for (int c=18;c<36;c++) if ((c&1)==s) l1[n1++]=c;
        for (int c=0;c<18;c++)  if ((c&1)==s) l2[n2++]=c;
    } else {
        for (int c=18;c<25;c++) if ((c&1)==s) l1[n1++]=c;
        for (int c=0;c<18;c++)  if ((c&1)==s) l2[n2++]=c;
    }

    if (L == 0)      waitge(&g_cA, NT0*t);
    else if (L == 1) waitge(&g_cB, NT1*t);
    else             waitge(&g_cC, NT2*t);
    mma_chunks(sb, Ab, Bb, l1, n1, acc);
    if (L == 1){ waitge(&g_cA, NT0*(t+1)); mma_chunks(sb, Ab, Bb, l2, n2, acc); }
    if (L == 2){ waitge(&g_cB, NT1*(t+1)); mma_chunks(sb, Ab, Bb, l2, n2, acc); }

    // ---- partials: warp w owns rows [w*16, w*16+16) ----
    const int w = tid>>5, ln = tid&31;
    __syncthreads();
    if (L == 0){
        float* sacc = (float*)sm;     // aliases stage buffers (idle now)
        {
            int row = w*16 + (ln>>2);
#pragma unroll
            for (int ni=0;ni<4;ni++){
                int col = ni*8 + (ln&3)*2;
                *(float2*)(sacc + row*32 + col)     = make_float2(acc[ni][0], acc[ni][1]);
                *(float2*)(sacc + (row+8)*32 + col) = make_float2(acc[ni][2], acc[ni][3]);
            }
        }
        __syncthreads();
    } else {
        float* P = ((L==1) ? gPart1[par] : gPart2[par]) + (size_t)(jb*2+s)*4096;
        {
            int row = w*16 + (ln>>2);
#pragma unroll
            for (int ni=0;ni<4;ni++){
                int col = ni*8 + (ln&3)*2;
                *(float2*)(P + row*32 + col)     = make_float2(acc[ni][0], acc[ni][1]);
                *(float2*)(P + (row+8)*32 + col) = make_float2(acc[ni][2], acc[ni][3]);
            }
        }
        __threadfence();
        __syncthreads();
        int* jc = &g_jbc[((L==1) ? 0 : 36) + jb];
        if (tid == 0){
            atomicAdd(jc, 1);
            while (ld_acq(jc) < 2*(t+1)) __nanosleep(32);
        }
        __syncthreads();
    }

    // ---- backpressure (acyclic; references strictly earlier steps) ----
    if (L == 0 && t >= 2) waitge(&g_cB, NT1*(t-1));
    if (L == 1 && t >= 2) waitge(&g_cC, NT2*(t-1));

    // ---- pointwise on this CTA's j-slice ----
    constexpr int JS = (L==0) ? 32 : 16;
    const int j0 = jb*32 + s*JS;
    __half* shi = (__half*)(sm + 16384);
    __half* slo = (__half*)(sm + 20608);
    float*  sf  = (float*)(sm + 24832);
    float* cst = g_c[L];
    constexpr int IT = JS*32/256;
#pragma unroll
    for (int it=0; it<IT; ++it){
        int item = tid + it*256;
        int ljj = item>>5, b = item&31;
        int j = j0 + ljj;
        int jj = s*JS + ljj;
        float hv = 0.f;
        if (j < C::OUT){
            float pre[4];
            if (L == 0){
                const float* sacc = (const float*)sm;
#pragma unroll
                for (int g=0; g<4; ++g) pre[g] = sacc[(g*32+jj)*32 + b];
            } else {
                const float* Pb = ((L==1) ? gPart1[par] : gPart2[par]) + (size_t)jb*2*4096;
#pragma unroll
                for (int g=0; g<4; ++g)
                    pre[g] = ldcg(Pb + (g*32+jj)*32 + b) + ldcg(Pb + 4096 + (g*32+jj)*32 + b);
            }
            float ip, fp, op, gp;
            if (L == 0){
                const float* p0 = g_P0 + ((size_t)t*M4H)*32 + b;
                ip = pre[0] + p0[(size_t)(j       )*32] + bhh[j];
                fp = pre[1] + p0[(size_t)(HH   + j)*32] + bhh[HH + j];
                op = pre[2] + p0[(size_t)(2*HH + j)*32] + bhh[2*HH + j];
                gp = pre[3] + p0[(size_t)(3*HH + j)*32] + bhh[3*HH + j];
            } else {
                ip = pre[0] + bx[j]            + bhh[j];
                fp = pre[1] + bx[C::OUT + j]   + bhh[C::OUT + j];
                op = pre[2] + bx[2*C::OUT + j] + bhh[2*C::OUT + j];
                gp = pre[3] + bx[3*C::OUT + j] + bhh[3*C::OUT + j];
            }
            float gi=1.f/(1.f+expf(-ip)), gf=1.f/(1.f+expf(-fp));
            float go=1.f/(1.f+expf(-op)), gg=tanhf(gp);
            float cn = gf*cst[j*32+b] + gi*gg;
            cst[j*32+b] = cn;
            hv = go*tanhf(cn);
            g_hf[L][j*32+b] = hv;
        }
        __half hbf = __float2half(hv);
        shi[ljj*33+b] = hbf;
        slo[ljj*33+b] = __float2half(hv - __half2float(hbf));
        if (L == 2) sf[ljj*33+b] = hv;
    }
    __syncthreads();

    // ---- packed staging stores ----
    constexpr int NBLK = JS/8;
    if (L != 2){
        const int total = 2*32*NBLK;
        for (int idx=tid; idx<total; idx+=256){
            int tgt = idx / (32*NBLK);
            int rem = idx % (32*NBLK);
            int b = rem & 31, bq = rem >> 5;
            __half* base; int kabs0;
            if (L == 0){ base = tgt ? gB1[par] : gB0[par^1]; kabs0 = j0; }
            else       { base = tgt ? gB2[par] : gB1[par^1]; kabs0 = tgt ? j0 : 1152 + j0; }
            int kabs = kabs0 + bq*8;
            int c = kabs >> 6, kk = kabs & 63;
            size_t pos = (size_t)c*4096 + (SWZ((uint32_t)(b*128 + kk*2)) >> 1);
            int r0 = bq*8;
            uint4 qh = make_uint4(
                pkhf(shi[(r0+0)*33+b], shi[(r0+1)*33+b]),
                pkhf(shi[(r0+2)*33+b], shi[(r0+3)*33+b]),
                pkhf(shi[(r0+4)*33+b], shi[(r0+5)*33+b]),
                pkhf(shi[(r0+6)*33+b], shi[(r0+7)*33+b]));
            uint4 ql = make_uint4(
                pkhf(slo[(r0+0)*33+b], slo[(r0+1)*33+b]),
                pkhf(slo[(r0+2)*33+b], slo[(r0+3)*33+b]),
                pkhf(slo[(r0+4)*33+b], slo[(r0+5)*33+b]),
                pkhf(slo[(r0+6)*33+b], slo[(r0+7)*33+b]));
            *(uint4*)(base + pos)        = qh;
            *(uint4*)(base + pos + 2048) = ql;
        }
    } else {
        if (tid < 64 && j0 < C::OUT){
            int b = tid & 31, bq = tid >> 5;
            int kabs = 1152 + j0 + bq*8;
            int c = kabs >> 6, kk = kabs & 63;
            size_t pos = (size_t)c*4096 + (SWZ((uint32_t)(b*128 + kk*2)) >> 1);
            int r0 = bq*8;
            uint4 qh = make_uint4(
                pkhf(shi[(r0+0)*33+b], shi[(r0+1)*33+b]),
                pkhf(shi[(r0+2)*33+b], shi[(r0+3)*33+b]),
                pkhf(shi[(r0+4)*33+b], shi[(r0+5)*33+b]),
                pkhf(shi[(r0+6)*33+b], shi[(r0+7)*33+b]));
            uint4 ql = make_uint4(
                pkhf(slo[(r0+0)*33+b], slo[(r0+1)*33+b]),
                pkhf(slo[(r0+2)*33+b], slo[(r0+3)*33+b]),
                pkhf(slo[(r0+4)*33+b], slo[(r0+5)*33+b]),
                pkhf(slo[(r0+6)*33+b], slo[(r0+7)*33+b]));
            __half* base = gB2[par^1];
            *(uint4*)(base + pos)        = qh;
            *(uint4*)(base + pos + 2048) = ql;
        }
        {
            int b = tid & 31, bq = tid >> 5;
            if (tid < 128 && j0 < C::OUT){
                float4 f = make_float4(sf[(bq*4+0)*33+b], sf[(bq*4+1)*33+b],
                                       sf[(bq*4+2)*33+b], sf[(bq*4+3)*33+b]);
                *(float4*)(g_h2all + (size_t)(t*32 + b)*EE + j0 + bq*4) = f;
            }
        }
    }

    __threadfence();
    __syncthreads();
    if (tid == 0){
        if (L == 0)      atomicAdd(&g_cA, 1);
        else if (L == 1) atomicAdd(&g_cB, 1);
        else             atomicAdd(&g_cC, 1);
    }
}

// =======================================================================
// Persistent spatially-pipelined recurrence: 36 L0 + 72 L1 + 26 L2 CTAs
// =======================================================================
__global__ __launch_bounds__(256) void recurrence(
    const float* __restrict__ bh0,
    const float* __restrict__ bi1, const float* __restrict__ bh1,
    const float* __restrict__ bi2, const float* __restrict__ bh2)
{
    extern __shared__ __align__(128) char sm[];
    const int blk = blockIdx.x;

    if (blk < NT0){
        for (int t=0; t<TT; ++t) step_layer<0>(sm, nullptr, bh0, t, blk, 0);
    } else if (blk < NT0 + NT1){
        int r = blk - NT0;
        for (int t=0; t<TT; ++t) step_layer<1>(sm, bi1, bh1, t, r>>1, r&1);
    } else {
        int r = blk - NT0 - NT1;
        for (int t=0; t<TT; ++t) step_layer<2>(sm, bi2, bh2, t, r>>1, r&1);
    }

    // ---- replay-safe shutdown: reset all counters ----
    __syncthreads();
    if (threadIdx.x == 0){
        atomicAdd(&g_end[0], 1);
        if (blk == 0){
            while (ld_acq(&g_end[0]) < NTOT) __nanosleep(128);
            g_cA = 0; g_cB = 0; g_cC = 0;
            for (int i=0;i<49;i++) g_jbc[i] = 0;
            g_end[0] = 0;
            __threadfence();
            atomicExch(&g_end[1], 1);
            while (ld_acq(&g_end[2]) < NTOT-1) __nanosleep(128);
            g_end[2] = 0;
            __threadfence();
            atomicExch(&g_end[1], 0);
        } else {
            while (ld_acq(&g_end[1]) == 0) __nanosleep(128);
            atomicAdd(&g_end[2], 1);
        }
    }
}

// ---- init / finalize ----
__global__ void init_states(const float* __restrict__ h0,
                            const float* __restrict__ c0,
                            const float* __restrict__ h0l,
                            const float* __restrict__ c0l)
{
    int idx = blockIdx.x*blockDim.x + threadIdx.x;
    if (idx < HH*BB){
        int k = idx>>5, b = idx&31;
        g_c[0][idx] = c0[b*HH + k];
        g_c[1][idx] = c0[BB*HH + b*HH + k];
        stageB(gB0[0], k,        b, h0[b*HH + k]);
        stageB(gB1[0], 1152 + k, b, h0[BB*HH + b*HH + k]);
    }
    if (idx < EE*BB){
        int k = idx>>5, b = idx&31;
        g_c[2][idx] = c0l[b*EE + k];
        stageB(gB2[0], 1152 + k, b, h0l[b*EE + k]);
    }
}

__global__ void finalize_states(float* __restrict__ out)
{
    const size_t D1 = (size_t)TT*BB*VV;
    const size_t D2 = D1 + 2*BB*HH;
    const size_t D3 = D2 + BB*EE;
    const size_t D4 = D3 + 2*BB*HH;
    int idx = blockIdx.x*blockDim.x + threadIdx.x;
    if (idx < HH*BB){
        int k = idx>>5, b = idx&31;
        out[D1 + b*HH + k]           = g_hf[0][idx];
        out[D1 + BB*HH + b*HH + k]   = g_hf[1][idx];
        out[D3 + b*HH + k]           = g_c[0][idx];
        out[D3 + BB*HH + b*HH + k]   = g_c[1][idx];
    }
    if (idx < EE*BB){
        int k = idx>>5, b = idx&31;
        out[D2 + b*EE + k] = g_hf[2][idx];
        out[D4 + b*EE + k] = g_c[2][idx];
    }
}

// =======================================================================
extern "C" void kernel_launch(void* const* d_in, const int* in_sizes, int n_in,
                              void* d_out, int out_size)
{
    const int*   x    = (const int*)  d_in[0];
    const float* h0   = (const float*)d_in[1];
    const float* c0   = (const float*)d_in[2];
    const float* h0l  = (const float*)d_in[3];
    const float* c0l  = (const float*)d_in[4];
    const float* emb  = (const float*)d_in[5];
    const float* Wi0  = (const float*)d_in[6];
    const float* bi0  = (const float*)d_in[7];
    const float* Wh0  = (const float*)d_in[8];
    const float* bh0  = (const float*)d_in[9];
    const float* Wi1  = (const float*)d_in[10];
    const float* bi1  = (const float*)d_in[11];
    const float* Wh1  = (const float*)d_in[12];
    const float* bh1  = (const float*)d_in[13];
    const float* Wi2  = (const float*)d_in[14];
    const float* bi2  = (const float*)d_in[15];
    const float* Wh2  = (const float*)d_in[16];
    const float* bh2  = (const float*)d_in[17];
    const float* decW = (const float*)d_in[18];
    const float* decb = (const float*)d_in[19];
    float* out = (float*)d_out;

    cudaFuncSetAttribute(recurrence, cudaFuncAttributeMaxDynamicSharedMemorySize, SMEM_MMA);

    init_states<<<(HH*BB + 255)/256, 256>>>(h0, c0, h0l, c0l);

    prep_A<0><<<(36*18*8192 + 255)/256, 256>>>(nullptr, Wh0);
    prep_A<1><<<(36*36*8192 + 255)/256, 256>>>(Wi1, Wh1);
    prep_A<2><<<(13*25*8192 + 255)/256, 256>>>(Wi2, Wh2);

    {   // P0 = emb[x] @ Wi0^T + bi0 (written transposed [t][col][b])
        dim3 g((M4H + 63)/64, NROW/64);
        sgemm_nt<0><<<g, 256>>>(emb, x, Wi0, bi0, nullptr, M4H);
    }

    recurrence<<<NTOT, 256, SMEM_MMA>>>(bh0, bi1, bh1, bi2, bh2);

    {   // decoder
        dim3 g((VV + 63)/64, NROW/64);
        sgemm_nt<1><<<g, 256>>>(nullptr, nullptr, decW, decb, out, VV);
    }

    finalize_states<<<(HH*BB + 255)/256, 256>>>(out);
}